// round 14
// baseline (speedup 1.0000x reference)
#include <cuda_runtime.h>
#include <math.h>

#define Bsz   4
#define Npts  8192
#define Mpts  2048
#define CIN   128
#define COUT  256
#define KNB   32
#define NDIR  32
#define HALF  128
#define BNEPS 1e-5f
#define BQ_R2 0.01f
#define FULLMASK 0xffffffffu

#define FPS_NT 512                     // FPS threads per CTA
#define FPS_PT (Npts / FPS_NT)         // 16 points per thread

// FPS dyn smem: sp4 (N float4 [k][t]) + center history (Mpts float4) + hist
#define FPS_DYN (Npts * 16 + Mpts * 16 + 520 * 4)

typedef unsigned long long ull;
typedef unsigned int uint;

// ---------------- scratch (device globals; no runtime allocation) ----------
__device__ int   g_idx [Bsz * Mpts];
__device__ float g_fi  [(size_t)Bsz * CIN * Mpts];     // (B, Cin, M)
__device__ float g_f1t [(size_t)Bsz * Npts * COUT];    // (B, N, Cout) n-major
__device__ int   g_qidx[Bsz * Mpts * KNB];
__device__ float g_tmax[(size_t)Bsz * NDIR * Mpts];    // (B, D, M)
__device__ float g_h   [(size_t)Bsz * HALF * Mpts];    // (B, 128, M)

// exact XLA-style distance: ((dx*dx + dy*dy) + dz*dz), rn, no FMA contraction
__device__ __forceinline__ float dist2_exact(float dx, float dy, float dz) {
    return __fadd_rn(__fadd_rn(__fmul_rn(dx, dx), __fmul_rn(dy, dy)),
                     __fmul_rn(dz, dz));
}

// ---------------- f32x2 packed helpers (exact per-element rn) --------------
__device__ __forceinline__ ull pack2(float lo, float hi) {
    ull r; asm("mov.b64 %0, {%1, %2};" : "=l"(r) : "f"(lo), "f"(hi)); return r;
}
__device__ __forceinline__ void unpack2(ull v, uint& lo, uint& hi) {
    asm("mov.b64 {%0, %1}, %2;" : "=r"(lo), "=r"(hi) : "l"(v));
}
__device__ __forceinline__ ull add2(ull a, ull b) {
    ull r; asm("add.rn.f32x2 %0, %1, %2;" : "=l"(r) : "l"(a), "l"(b)); return r;
}
__device__ __forceinline__ ull mul2(ull a, ull b) {
    ull r; asm("mul.rn.f32x2 %0, %1, %2;" : "=l"(r) : "l"(a), "l"(b)); return r;
}
__device__ __forceinline__ uint redux_max_u32(uint v) {
    uint r; asm("redux.sync.max.u32 %0, %1, 0xffffffff;" : "=r"(r) : "r"(v)); return r;
}
__device__ __forceinline__ uint redux_min_u32(uint v) {
    uint r; asm("redux.sync.min.u32 %0, %1, 0xffffffff;" : "=r"(r) : "r"(v)); return r;
}

// ============================================================================
// Kernel A: blocks 0..3 = FPS (512 thr, 16 pts/thr, thin-skip, smem history);
//           blocks 4..  = conv1 GEMM (512 thr, runs in FPS's shadow).
// ============================================================================
__global__ __launch_bounds__(FPS_NT, 1)
void fps_conv1_kernel(const float* __restrict__ p,
                      const float* __restrict__ f,
                      const float* __restrict__ w,      // conv1_w (256,128)
                      const float* __restrict__ bias,   // conv1_b (256)
                      float* __restrict__ newp)         // d_out head (B,M,3)
{
    extern __shared__ char dsm[];
    __shared__ float sA[32 * 64];      // conv1 only
    __shared__ float sW[32 * 257];     // conv1 only
    __shared__ uint   swv[16];         // FPS: per-warp max bits (persistent)
    __shared__ uint   swi[16];         // FPS: per-warp argmax orig index
    __shared__ float4 swc[16];         // FPS: per-warp winner coords
    __shared__ float4 scen;            // FPS: current center

    if (blockIdx.x < Bsz) {
        // ----------------------------- FPS -------------------------------
        float4* sp4  = (float4*)dsm;                        // [k][t]: k*512+t
        float4* shist = (float4*)(dsm + Npts * 16);         // Mpts centers
        uint*   hist = (uint*)(dsm + Npts * 16 + Mpts * 16);// 513

        const int b = blockIdx.x;
        const float* pb = p + (size_t)b * Npts * 3;
        const int t = threadIdx.x, lane = t & 31, wrp = t >> 5;

        // ---- preamble: counting-sort into 512 MORTON-ordered bins ----
        if (t < 512) hist[t] = 0;
        __syncthreads();
        {
#pragma unroll
            for (int k = 0; k < FPS_PT; k++) {
                int i = k * FPS_NT + t;
                float x = pb[3 * i], y = pb[3 * i + 1], z = pb[3 * i + 2];
                uint bx = (uint)(int)fminf(fmaxf(x, 0.f) * 8.f, 7.f);
                uint by = (uint)(int)fminf(fmaxf(y, 0.f) * 8.f, 7.f);
                uint bz = (uint)(int)fminf(fmaxf(z, 0.f) * 8.f, 7.f);
                uint bin = ((bx & 4u) << 6) | ((bx & 2u) << 4) | ((bx & 1u) << 2)
                         | ((by & 4u) << 5) | ((by & 2u) << 3) | ((by & 1u) << 1)
                         | ((bz & 4u) << 4) | ((bz & 2u) << 2) |  (bz & 1u);
                atomicAdd(&hist[bin], 1u);
                // stash bin in shist scratch to avoid recompute (reuse as tmp)
                ((uint*)&shist[0])[i] = bin;
            }
            __syncthreads();
            if (t == 0) {                  // serial exclusive scan (once)
                uint run = 0;
                for (int j = 0; j < 512; j++) {
                    uint c = hist[j]; hist[j] = run; run += c;
                }
            }
            __syncthreads();
#pragma unroll
            for (int k = 0; k < FPS_PT; k++) {
                int i = k * FPS_NT + t;
                uint bin = ((uint*)&shist[0])[i];
                float x = pb[3 * i], y = pb[3 * i + 1], z = pb[3 * i + 2];
                uint pos = atomicAdd(&hist[bin], 1u);
                uint dst = (pos & (uint)(FPS_PT - 1)) * FPS_NT + (pos / FPS_PT);
                sp4[dst] = make_float4(x, y, z, __uint_as_float((uint)i));
            }
        }
        __syncthreads();

        // ---- load my 16 sorted points into packed registers + warp bbox ----
        ull PX[FPS_PT / 2], PY[FPS_PT / 2], PZ[FPS_PT / 2];
        uint D[FPS_PT];
        float wlox, whix, wloy, whiy, wloz, whiz;
        {
            float alox = 1e30f, ahix = -1e30f, aloy = 1e30f, ahiy = -1e30f;
            float aloz = 1e30f, ahiz = -1e30f;
#pragma unroll
            for (int j = 0; j < FPS_PT / 2; j++) {
                float4 q0 = sp4[(2 * j) * FPS_NT + t];
                float4 q1 = sp4[(2 * j + 1) * FPS_NT + t];
                PX[j] = pack2(q0.x, q1.x);
                PY[j] = pack2(q0.y, q1.y);
                PZ[j] = pack2(q0.z, q1.z);
                D[2 * j] = __float_as_uint(1e10f);
                D[2 * j + 1] = __float_as_uint(1e10f);
                alox = fminf(alox, fminf(q0.x, q1.x));
                ahix = fmaxf(ahix, fmaxf(q0.x, q1.x));
                aloy = fminf(aloy, fminf(q0.y, q1.y));
                ahiy = fmaxf(ahiy, fmaxf(q0.y, q1.y));
                aloz = fminf(aloz, fminf(q0.z, q1.z));
                ahiz = fmaxf(ahiz, fmaxf(q0.z, q1.z));
            }
#pragma unroll
            for (int off = 16; off > 0; off >>= 1) {
                alox = fminf(alox, __shfl_xor_sync(FULLMASK, alox, off));
                ahix = fmaxf(ahix, __shfl_xor_sync(FULLMASK, ahix, off));
                aloy = fminf(aloy, __shfl_xor_sync(FULLMASK, aloy, off));
                ahiy = fmaxf(ahiy, __shfl_xor_sync(FULLMASK, ahiy, off));
                aloz = fminf(aloz, __shfl_xor_sync(FULLMASK, aloz, off));
                ahiz = fmaxf(ahiz, __shfl_xor_sync(FULLMASK, ahiz, off));
            }
            wlox = alox; whix = ahix; wloy = aloy; whiy = ahiy;
            wloz = aloz; whiz = ahiz;
        }

        uint wmaxc = __float_as_uint(1e10f);   // this warp's own cached max

        if (t == 0) {
            float x0 = __ldg(&pb[0]), y0 = __ldg(&pb[1]), z0 = __ldg(&pb[2]);
            scen = make_float4(x0, y0, z0, 0.f);
            shist[0] = make_float4(x0, y0, z0, __uint_as_float(0u));
        }
        __syncthreads();

        for (int m = 1; m < Mpts; m++) {
            // center chosen at m-1 (broadcast LDS)
            const float4 c = scen;
            const float cx = c.x, cy = c.y, cz = c.z;

            // ---- warp-uniform thin skip test ----
            float gx = fmaxf(fmaxf(wlox - cx, cx - whix), 0.f);
            float gy = fmaxf(fmaxf(wloy - cy, cy - whiy), 0.f);
            float gz = fmaxf(fmaxf(wloz - cz, cz - whiz), 0.f);
            float d2m = gx * gx + gy * gy + gz * gz;
            if (!(d2m * 0.99f >= __uint_as_float(wmaxc))) {
                // ---- packed exact-rn update of my 16 distances ----
                ull ncx = pack2(-cx, -cx), ncy = pack2(-cy, -cy), ncz = pack2(-cz, -cz);
#pragma unroll
                for (int pr = 0; pr < FPS_PT / 2; pr++) {
                    ull dx = add2(PX[pr], ncx);
                    ull dy = add2(PY[pr], ncy);
                    ull dz = add2(PZ[pr], ncz);
                    ull d2 = add2(add2(mul2(dx, dx), mul2(dy, dy)), mul2(dz, dz));
                    uint lo, hi; unpack2(d2, lo, hi);
                    uint a = D[2 * pr];       D[2 * pr]     = (lo < a) ? lo : a;
                    uint cc2 = D[2 * pr + 1]; D[2 * pr + 1] = (hi < cc2) ? hi : cc2;
                }
                // per-thread argmax scan, original-index tie-break from sp4.w
                uint bd = 0, bg = 0; int bk = 0;
#pragma unroll
                for (int k = 0; k < FPS_PT; k++) {
                    uint gi = *(const uint*)((const char*)sp4
                                             + ((size_t)(k * FPS_NT + t) * 16u + 12u));
                    uint nw = D[k];
                    bool better = (k == 0) || (nw > bd) || (nw == bd && gi < bg);
                    if (better) { bd = nw; bg = gi; bk = k; }
                }
                // warp argmax + refresh persistent per-warp entries
                uint wmax = redux_max_u32(bd);
                uint cand = (bd == wmax) ? bg : 0xffffffffu;
                uint widx = redux_min_u32(cand);
                if (bd == wmax && bg == widx) {           // unique owner lane
                    swc[wrp] = sp4[bk * FPS_NT + t];
                }
                if (lane == 0) { swv[wrp] = wmax; swi[wrp] = widx; }
                wmaxc = wmax;
            }
            __syncthreads();                              // BAR_a

            if (wrp == 0) {
                uint v  = (lane < 16) ? swv[lane] : 0u;
                uint ii = (lane < 16) ? swi[lane] : 0xffffffffu;
                uint gm = redux_max_u32(v);
                uint c2 = (v == gm) ? ii : 0xffffffffu;
                uint bi = redux_min_u32(c2);
                uint wm = __ballot_sync(FULLMASK, c2 == bi);  // winner warps
                int  wwin = __ffs(wm) - 1;                    // uniform
                float4 cc = swc[wwin];                        // broadcast LDS.128
                if (lane == 0) {
                    scen = make_float4(cc.x, cc.y, cc.z, 0.f);
                    shist[m] = make_float4(cc.x, cc.y, cc.z,
                                           __uint_as_float(bi));
                }
            }
            __syncthreads();                              // BAR_b
        }

        // ---- final parallel writeback of centers + indices ----
        for (int m = t; m < Mpts; m += FPS_NT) {
            float4 h = shist[m];
            float* o = newp + (size_t)(b * Mpts + m) * 3;
            o[0] = h.x; o[1] = h.y; o[2] = h.z;
            g_idx[b * Mpts + m] = (int)__float_as_uint(h.w);
        }
    } else {
        // ------------------- conv1: f1t[b][n][c] = W @ f + bias ----------
        const int bc = blockIdx.x - Bsz;
        const int b  = bc >> 7;                 // 128 x-tiles per batch
        const int x0 = (bc & 127) * 64;
        const int t  = threadIdx.x;
        const int tx = t & 31;                  // c = tx + 32k
        const int ty = t >> 5;                  // x = x0 + ty*4 + e (ty 0..15)
        const float* fb = f + (size_t)b * CIN * Npts;

        float acc[4][8];
#pragma unroll
        for (int e = 0; e < 4; e++)
#pragma unroll
            for (int k = 0; k < 8; k++) acc[e][k] = 0.f;

        for (int cic = 0; cic < CIN; cic += 32) {
#pragma unroll
            for (int e = 0; e < 4; e++) {
                int lin = e * 512 + t;
                int ci = lin >> 6, xl = lin & 63;
                sA[ci * 64 + xl] = fb[(size_t)(cic + ci) * Npts + x0 + xl];
            }
#pragma unroll
            for (int e = 0; e < 16; e++) {
                int lin = e * 512 + t;
                int c = lin >> 5, ci = lin & 31;
                sW[ci * 257 + c] = w[c * CIN + cic + ci];
            }
            __syncthreads();
#pragma unroll
            for (int ci = 0; ci < 32; ci++) {
                float a0 = sA[ci * 64 + ty * 4 + 0];
                float a1 = sA[ci * 64 + ty * 4 + 1];
                float a2 = sA[ci * 64 + ty * 4 + 2];
                float a3 = sA[ci * 64 + ty * 4 + 3];
#pragma unroll
                for (int k = 0; k < 8; k++) {
                    float wv = sW[ci * 257 + tx + 32 * k];
                    acc[0][k] = fmaf(a0, wv, acc[0][k]);
                    acc[1][k] = fmaf(a1, wv, acc[1][k]);
                    acc[2][k] = fmaf(a2, wv, acc[2][k]);
                    acc[3][k] = fmaf(a3, wv, acc[3][k]);
                }
            }
            __syncthreads();
        }
#pragma unroll
        for (int e = 0; e < 4; e++) {
            int x = x0 + ty * 4 + e;
            float* orow = g_f1t + (size_t)(b * Npts + x) * COUT;
#pragma unroll
            for (int k = 0; k < 8; k++) {
                int c = tx + 32 * k;
                orow[c] = acc[e][k] + bias[c];
            }
        }
    }
}

// ============================================================================
// Kernel B: blocks x<128: ball query + dpn + theta + tmax (warp per center);
//           blocks x>=128: gather fi[b][ci][m] = f[b][ci][idx[b][m]].
// ============================================================================
#define BALLQ_SMEM ((3 * Npts + 3 * NDIR + 16 * KNB) * 4)

__global__ __launch_bounds__(512)
void ballq_gather_kernel(const float* __restrict__ p,
                         const float* __restrict__ newp,
                         const float* __restrict__ dirs,
                         const float* __restrict__ f)
{
    extern __shared__ float sh[];
    const int b = blockIdx.y;
    const int t = threadIdx.x;

    if (blockIdx.x >= Mpts / 16) {
        // ---------------- gather fi ----------------
        const int ci = blockIdx.x - Mpts / 16;
        const float* fb = f + (size_t)(b * CIN + ci) * Npts;
        float* ob = g_fi + (size_t)(b * CIN + ci) * Mpts;
        const int* ib = g_idx + b * Mpts;
        for (int m = t; m < Mpts; m += 512)
            ob[m] = fb[ib[m]];
        return;
    }

    float* spx = sh;
    float* spy = sh + Npts;
    float* spz = sh + 2 * Npts;
    float* sdx = sh + 3 * Npts;
    float* sdy = sdx + NDIR;
    float* sdz = sdy + NDIR;
    int*   sq  = (int*)(sdz + NDIR);

    const int w = t >> 5, lane = t & 31;
    const float* pb = p + (size_t)b * Npts * 3;

    for (int n = t; n < Npts; n += 512) {
        spx[n] = pb[3 * n];
        spy[n] = pb[3 * n + 1];
        spz[n] = pb[3 * n + 2];
    }
    if (t < NDIR) {
        float dx = dirs[3 * t], dy = dirs[3 * t + 1], dz = dirs[3 * t + 2];
        float nm = sqrtf(dx * dx + dy * dy + dz * dz);
        float inv = 1.0f / fmaxf(nm, 1e-12f);
        sdx[t] = dx * inv; sdy[t] = dy * inv; sdz[t] = dz * inv;
    }
    __syncthreads();

    const int m = blockIdx.x * 16 + w;
    const float* cp = newp + (size_t)(b * Mpts + m) * 3;
    const float cx = cp[0], cy = cp[1], cz = cp[2];

    int cnt = 0;
    int* q = sq + w * KNB;
    for (int ch = 0; ch < Npts / 32; ch++) {
        int n = ch * 32 + lane;
        float dx = spx[n] - cx, dy = spy[n] - cy, dz = spz[n] - cz;
        float d2 = dist2_exact(dx, dy, dz);
        bool pred = d2 < BQ_R2;
        unsigned mask = __ballot_sync(FULLMASK, pred);
        if (pred) {
            int pos = cnt + __popc(mask & ((1u << lane) - 1u));
            if (pos < KNB) q[pos] = n;
        }
        cnt += __popc(mask);
        if (cnt >= KNB) break;
    }
    __syncwarp();
    int eff = cnt < KNB ? cnt : KNB;
    int myn = q[lane < eff ? lane : 0];
    g_qidx[(b * Mpts + m) * KNB + lane] = myn;

    float dx = spx[myn] - cx, dy = spy[myn] - cy, dz = spz[myn] - cz;
    float nm = sqrtf(dx * dx + dy * dy + dz * dz);
    float inv = 1.0f / fmaxf(nm, 1e-12f);
    float ux = dx * inv, uy = dy * inv, uz = dz * inv;

    float mytm = 0.f;
#pragma unroll
    for (int d = 0; d < NDIR; d++) {
        float th = ux * sdx[d] + uy * sdy[d] + uz * sdz[d];
#pragma unroll
        for (int off = 16; off > 0; off >>= 1)
            th = fmaxf(th, __shfl_xor_sync(FULLMASK, th, off));
        if (lane == d) mytm = th;
    }
    g_tmax[((size_t)b * NDIR + lane) * Mpts + m] = mytm;
}

// ============================================================================
// Shared GEMM body: out[b][c][x] = sum_ci W[c][ci]*A[b][ci][x] (+epilogue)
// mode 0: identity  (A=g_fi,   out=outf, write acc+bias)
// mode 1: h         (A=g_tmax, out=g_h,  bn + exact gelu)
// mode 2: pe        (A=g_h,    out=outf, out += acc+bias)
// ============================================================================
__device__ __forceinline__
void gemm_body(const float* __restrict__ W, const float* __restrict__ bias,
               const float* __restrict__ bg, const float* __restrict__ bb,
               const float* __restrict__ bm, const float* __restrict__ bvv,
               float* __restrict__ outf, int Cin, int Cout, int mode, int co0,
               float* sA, float* sW)
{
    const int b = blockIdx.z;
    const int m0 = blockIdx.x * 64;
    const int t = threadIdx.x, tx = t & 15, ty = t >> 4;

    const float* A = (mode == 0) ? g_fi : (mode == 1 ? g_tmax : g_h);
    float* out = (mode == 1) ? g_h : outf;
    const float* Ab = A + (size_t)b * Cin * Mpts;

    float acc[4][4];
#pragma unroll
    for (int j = 0; j < 4; j++)
#pragma unroll
        for (int i = 0; i < 4; i++) acc[j][i] = 0.f;

    for (int cic = 0; cic < Cin; cic += 32) {
#pragma unroll
        for (int e = 0; e < 8; e++) {
            int lin = e * 256 + t;
            int ci = lin >> 6, xl = lin & 63;
            sA[ci * 64 + xl] = Ab[(size_t)(cic + ci) * Mpts + m0 + xl];
            int co = lin >> 5, ci2 = lin & 31;
            sW[co * 33 + ci2] = W[(size_t)(co0 + co) * Cin + cic + ci2];
        }
        __syncthreads();
#pragma unroll
        for (int ci = 0; ci < 32; ci++) {
            float4 a = *(const float4*)&sA[ci * 64 + tx * 4];
#pragma unroll
            for (int j = 0; j < 4; j++) {
                float wv = sW[(ty * 4 + j) * 33 + ci];
                acc[j][0] = fmaf(wv, a.x, acc[j][0]);
                acc[j][1] = fmaf(wv, a.y, acc[j][1]);
                acc[j][2] = fmaf(wv, a.z, acc[j][2]);
                acc[j][3] = fmaf(wv, a.w, acc[j][3]);
            }
        }
        __syncthreads();
    }

#pragma unroll
    for (int j = 0; j < 4; j++) {
        int c = co0 + ty * 4 + j;
        size_t o = ((size_t)b * Cout + c) * Mpts + m0 + tx * 4;
        float r[4] = {acc[j][0], acc[j][1], acc[j][2], acc[j][3]};
        if (mode == 0) {
            float bc = bias[c];
            float4 v = make_float4(r[0] + bc, r[1] + bc, r[2] + bc, r[3] + bc);
            *(float4*)&out[o] = v;
        } else if (mode == 1) {
            float scale = bg[c] / sqrtf(bvv[c] + BNEPS);
            float mean = bm[c], off = bb[c];
            float4 v;
            float* pv = &v.x;
#pragma unroll
            for (int i = 0; i < 4; i++) {
                float y = (r[i] - mean) * scale + off;
                pv[i] = 0.5f * y * (1.0f + erff(y * 0.70710678118654752f));
            }
            *(float4*)&out[o] = v;
        } else {
            float bc = bias[c];
            float4 old = *(const float4*)&out[o];
            float4 v = make_float4(old.x + r[0] + bc, old.y + r[1] + bc,
                                   old.z + r[2] + bc, old.w + r[3] + bc);
            *(float4*)&out[o] = v;
        }
    }
}

// Combined identity (mode 0, y in [0,4)) + h (mode 1, y in [4,6)) launch.
__global__ __launch_bounds__(256)
void gemm01_kernel(const float* __restrict__ skip_w, const float* __restrict__ skip_b,
                   const float* __restrict__ de_w1,
                   const float* __restrict__ de_g, const float* __restrict__ de_bb,
                   const float* __restrict__ de_m, const float* __restrict__ de_v,
                   float* __restrict__ outf)
{
    __shared__ float sA[32 * 64];
    __shared__ float sW[64 * 33];
    if (blockIdx.y < COUT / 64) {
        gemm_body(skip_w, skip_b, nullptr, nullptr, nullptr, nullptr,
                  outf, CIN, COUT, 0, blockIdx.y * 64, sA, sW);
    } else {
        gemm_body(de_w1, nullptr, de_g, de_bb, de_m, de_v,
                  outf, NDIR, HALF, 1, (blockIdx.y - COUT / 64) * 64, sA, sW);
    }
}

// pe GEMM (mode 2)
__global__ __launch_bounds__(256)
void gemm2_kernel(const float* __restrict__ de_w2, const float* __restrict__ de_b2,
                  float* __restrict__ outf)
{
    __shared__ float sA[32 * 64];
    __shared__ float sW[64 * 33];
    gemm_body(de_w2, de_b2, nullptr, nullptr, nullptr, nullptr,
              outf, HALF, COUT, 2, blockIdx.y * 64, sA, sW);
}

// ============================================================================
// Kernel E: fj gather-max over K + bn1, += into outf. Warp per center m.
// ============================================================================
__global__ __launch_bounds__(1024)
void fjmax_kernel(const float* __restrict__ bg, const float* __restrict__ bb,
                  const float* __restrict__ bm, const float* __restrict__ bvv,
                  float* __restrict__ outf)
{
    __shared__ float st[COUT * 33];
    const int b = blockIdx.y, m0 = blockIdx.x * 32;
    const int t = threadIdx.x, w = t >> 5, lane = t & 31;
    const int m = m0 + w;

    int kn = g_qidx[(b * Mpts + m) * KNB + lane];
    int first = __shfl_sync(FULLMASK, kn, 0);

    float4 a0 = make_float4(-3.4e38f, -3.4e38f, -3.4e38f, -3.4e38f);
    float4 a1 = a0;
    for (int k = 0; k < KNB; k++) {
        int n = __shfl_sync(FULLMASK, kn, k);
        if (k > 0 && n == first) continue;   // uniform across warp
        const float4* row = (const float4*)(g_f1t + (size_t)(b * Npts + n) * COUT);
        float4 v0 = row[lane];
        float4 v1 = row[32 + lane];
        a0.x = fmaxf(a0.x, v0.x); a0.y = fmaxf(a0.y, v0.y);
        a0.z = fmaxf(a0.z, v0.z); a0.w = fmaxf(a0.w, v0.w);
        a1.x = fmaxf(a1.x, v1.x); a1.y = fmaxf(a1.y, v1.y);
        a1.z = fmaxf(a1.z, v1.z); a1.w = fmaxf(a1.w, v1.w);
    }
    const float* pa0 = &a0.x;
    const float* pa1 = &a1.x;
#pragma unroll
    for (int j = 0; j < 4; j++) {
        st[(lane * 4 + j) * 33 + w] = pa0[j];
        st[(128 + lane * 4 + j) * 33 + w] = pa1[j];
    }
    __syncthreads();

    const int c = t >> 2, part = t & 3;
    float scale = bg[c] / sqrtf(bvv[c] + BNEPS);
    float mean = bm[c], off = bb[c];
    float* o = outf + ((size_t)b * COUT + c) * Mpts + m0 + part * 8;
#pragma unroll
    for (int i = 0; i < 8; i++) {
        float x = st[c * 33 + part * 8 + i];
        o[i] += (x - mean) * scale + off;
    }
}

// ============================================================================
extern "C" void kernel_launch(void* const* d_in, const int* in_sizes, int n_in,
                              void* d_out, int out_size)
{
    const float* p       = (const float*)d_in[0];
    const float* f       = (const float*)d_in[1];
    const float* conv1_w = (const float*)d_in[2];
    const float* conv1_b = (const float*)d_in[3];
    const float* skip_w  = (const float*)d_in[4];
    const float* skip_b  = (const float*)d_in[5];
    const float* bn1_g   = (const float*)d_in[6];
    const float* bn1_b   = (const float*)d_in[7];
    const float* bn1_m   = (const float*)d_in[8];
    const float* bn1_v   = (const float*)d_in[9];
    const float* dirs    = (const float*)d_in[10];
    const float* de_w1   = (const float*)d_in[11];
    const float* de_g    = (const float*)d_in[12];
    const float* de_bb   = (const float*)d_in[13];
    const float* de_m    = (const float*)d_in[14];
    const float* de_v    = (const float*)d_in[15];
    const float* de_w2   = (const float*)d_in[16];
    const float* de_b2   = (const float*)d_in[17];

    float* outp = (float*)d_out;                 // new_p (B,M,3)
    float* outf = outp + Bsz * Mpts * 3;         // f_out (B,256,M)

    cudaFuncSetAttribute(fps_conv1_kernel,
                         cudaFuncAttributeMaxDynamicSharedMemorySize, FPS_DYN);
    cudaFuncSetAttribute(ballq_gather_kernel,
                         cudaFuncAttributeMaxDynamicSharedMemorySize, BALLQ_SMEM);

    // 1) FPS (4 blocks, 512 thr, 16 pts/thr) + conv1 GEMM (512 blocks)
    fps_conv1_kernel<<<Bsz + Bsz * 128, FPS_NT, FPS_DYN>>>(
        p, f, conv1_w, conv1_b, outp);
    // 2) ball query + theta + tmax  ||  gather fi   (one launch)
    ballq_gather_kernel<<<dim3(Mpts / 16 + CIN, Bsz), 512, BALLQ_SMEM>>>(
        p, outp, dirs, f);
    // 3) identity -> outf (write)  ||  h = gelu(bn(de_w1 @ tmax)) -> g_h
    gemm01_kernel<<<dim3(Mpts / 64, COUT / 64 + HALF / 64, Bsz), 256>>>(
        skip_w, skip_b, de_w1, de_g, de_bb, de_m, de_v, outf);
    // 4) pe: outf += de_w2 @ h + de_b2
    gemm2_kernel<<<dim3(Mpts / 64, COUT / 64, Bsz), 256>>>(de_w2, de_b2, outf);
    // 5) outf += bn1(max_k fj)
    fjmax_kernel<<<dim3(Mpts / 32, Bsz), 1024>>>(bn1_g, bn1_b, bn1_m, bn1_v, outf);
}

// round 15
// speedup vs baseline: 1.1054x; 1.1054x over previous
#include <cuda_runtime.h>
#include <math.h>

#define Bsz   4
#define Npts  8192
#define Mpts  2048
#define CIN   128
#define COUT  256
#define KNB   32
#define NDIR  32
#define HALF  128
#define BNEPS 1e-5f
#define BQ_R2 0.01f
#define FULLMASK 0xffffffffu

// FPS dyn smem: sp4 (N float4, [k][t] layout, .w = original index) + hist(513)
#define FPS_DYN (Npts * 16 + 513 * 4)

typedef unsigned long long ull;
typedef unsigned int uint;

// ---------------- scratch (device globals; no runtime allocation) ----------
__device__ int   g_idx [Bsz * Mpts];
__device__ float g_fi  [(size_t)Bsz * CIN * Mpts];     // (B, Cin, M)
__device__ float g_f1t [(size_t)Bsz * Npts * COUT];    // (B, N, Cout) n-major
__device__ int   g_qidx[Bsz * Mpts * KNB];
__device__ float g_tmax[(size_t)Bsz * NDIR * Mpts];    // (B, D, M)
__device__ float g_h   [(size_t)Bsz * HALF * Mpts];    // (B, 128, M)

// exact XLA-style distance: ((dx*dx + dy*dy) + dz*dz), rn, no FMA contraction
__device__ __forceinline__ float dist2_exact(float dx, float dy, float dz) {
    return __fadd_rn(__fadd_rn(__fmul_rn(dx, dx), __fmul_rn(dy, dy)),
                     __fmul_rn(dz, dz));
}

// ---------------- f32x2 packed helpers (exact per-element rn) --------------
__device__ __forceinline__ ull pack2(float lo, float hi) {
    ull r; asm("mov.b64 %0, {%1, %2};" : "=l"(r) : "f"(lo), "f"(hi)); return r;
}
__device__ __forceinline__ void unpack2(ull v, uint& lo, uint& hi) {
    asm("mov.b64 {%0, %1}, %2;" : "=r"(lo), "=r"(hi) : "l"(v));
}
__device__ __forceinline__ ull add2(ull a, ull b) {
    ull r; asm("add.rn.f32x2 %0, %1, %2;" : "=l"(r) : "l"(a), "l"(b)); return r;
}
__device__ __forceinline__ ull mul2(ull a, ull b) {
    ull r; asm("mul.rn.f32x2 %0, %1, %2;" : "=l"(r) : "l"(a), "l"(b)); return r;
}
__device__ __forceinline__ uint redux_max_u32(uint v) {
    uint r; asm("redux.sync.max.u32 %0, %1, 0xffffffff;" : "=r"(r) : "r"(v)); return r;
}
__device__ __forceinline__ uint redux_min_u32(uint v) {
    uint r; asm("redux.sync.min.u32 %0, %1, 0xffffffff;" : "=r"(r) : "r"(v)); return r;
}

// ============================================================================
// Kernel A: blocks 0..3 = FPS (one CTA/batch; thin-skip + warp0 combine);
//           blocks 4..  = conv1 GEMM (runs in FPS's shadow).
// ============================================================================
__global__ __launch_bounds__(1024, 1)
void fps_conv1_kernel(const float* __restrict__ p,
                      const float* __restrict__ f,
                      const float* __restrict__ w,      // conv1_w (256,128)
                      const float* __restrict__ bias,   // conv1_b (256)
                      float* __restrict__ newp)         // d_out head (B,M,3)
{
    extern __shared__ char dsm[];
    __shared__ float sA[32 * 64];      // conv1 only
    __shared__ float sW[32 * 257];     // conv1 only
    __shared__ uint   swv[32];         // FPS: per-warp max bits (persistent)
    __shared__ uint   swi[32];         // FPS: per-warp argmax orig index
    __shared__ float4 swc[32];         // FPS: per-warp winner coords
    __shared__ float4 scen;            // FPS: current center (x,y,z,idx)

    if (blockIdx.x < Bsz) {
        // ----------------------------- FPS -------------------------------
        float4* sp4  = (float4*)dsm;                   // [k][t]: k*1024+t
        uint*   hist = (uint*)(dsm + Npts * 16);       // 513

        const int b = blockIdx.x;
        const float* pb = p + (size_t)b * Npts * 3;
        const int t = threadIdx.x, lane = t & 31, wrp = t >> 5;

        // ---- preamble: counting-sort into 512 MORTON-ordered bins ----
        if (t < 512) hist[t] = 0;
        __syncthreads();
        {
            float lx[8], ly[8], lz[8];
            uint  lb[8];
#pragma unroll
            for (int k = 0; k < 8; k++) {
                int i = k * 1024 + t;
                lx[k] = pb[3 * i];
                ly[k] = pb[3 * i + 1];
                lz[k] = pb[3 * i + 2];
                uint bx = (uint)(int)fminf(fmaxf(lx[k], 0.f) * 8.f, 7.f);
                uint by = (uint)(int)fminf(fmaxf(ly[k], 0.f) * 8.f, 7.f);
                uint bz = (uint)(int)fminf(fmaxf(lz[k], 0.f) * 8.f, 7.f);
                lb[k] = ((bx & 4u) << 6) | ((bx & 2u) << 4) | ((bx & 1u) << 2)
                      | ((by & 4u) << 5) | ((by & 2u) << 3) | ((by & 1u) << 1)
                      | ((bz & 4u) << 4) | ((bz & 2u) << 2) |  (bz & 1u);
                atomicAdd(&hist[lb[k]], 1u);
            }
            __syncthreads();
            if (t == 0) {                  // serial exclusive scan (once)
                uint run = 0;
                for (int j = 0; j < 512; j++) {
                    uint c = hist[j]; hist[j] = run; run += c;
                }
            }
            __syncthreads();
#pragma unroll
            for (int k = 0; k < 8; k++) {
                uint pos = atomicAdd(&hist[lb[k]], 1u);
                uint dst = (pos & 7u) * 1024u + (pos >> 3);   // [k][t] layout
                sp4[dst] = make_float4(lx[k], ly[k], lz[k],
                                       __uint_as_float((uint)(k * 1024 + t)));
            }
        }
        __syncthreads();

        // ---- load my 8 sorted points into packed registers + warp bbox ----
        ull PX[4], PY[4], PZ[4];
        uint D[8];
        float wlox, whix, wloy, whiy, wloz, whiz;
        {
            float qx[8], qy[8], qz[8];
#pragma unroll
            for (int k = 0; k < 8; k++) {
                float4 q = sp4[k * 1024 + t];        // conflict-free
                qx[k] = q.x; qy[k] = q.y; qz[k] = q.z;
                D[k] = __float_as_uint(1e10f);
            }
#pragma unroll
            for (int j = 0; j < 4; j++) {
                PX[j] = pack2(qx[2 * j], qx[2 * j + 1]);
                PY[j] = pack2(qy[2 * j], qy[2 * j + 1]);
                PZ[j] = pack2(qz[2 * j], qz[2 * j + 1]);
            }
            float alox = qx[0], ahix = qx[0], aloy = qy[0], ahiy = qy[0];
            float aloz = qz[0], ahiz = qz[0];
#pragma unroll
            for (int k = 1; k < 8; k++) {
                alox = fminf(alox, qx[k]); ahix = fmaxf(ahix, qx[k]);
                aloy = fminf(aloy, qy[k]); ahiy = fmaxf(ahiy, qy[k]);
                aloz = fminf(aloz, qz[k]); ahiz = fmaxf(ahiz, qz[k]);
            }
#pragma unroll
            for (int off = 16; off > 0; off >>= 1) {
                alox = fminf(alox, __shfl_xor_sync(FULLMASK, alox, off));
                ahix = fmaxf(ahix, __shfl_xor_sync(FULLMASK, ahix, off));
                aloy = fminf(aloy, __shfl_xor_sync(FULLMASK, aloy, off));
                ahiy = fmaxf(ahiy, __shfl_xor_sync(FULLMASK, ahiy, off));
                aloz = fminf(aloz, __shfl_xor_sync(FULLMASK, aloz, off));
                ahiz = fmaxf(ahiz, __shfl_xor_sync(FULLMASK, ahiz, off));
            }
            wlox = alox; whix = ahix; wloy = aloy; whiy = ahiy;
            wloz = aloz; whiz = ahiz;
        }

        uint wmaxc = __float_as_uint(1e10f);   // this warp's own cached max

        if (t == 0) {
            float x0 = __ldg(&pb[0]), y0 = __ldg(&pb[1]), z0 = __ldg(&pb[2]);
            scen = make_float4(x0, y0, z0, 0.f);
            g_idx[b * Mpts] = 0;
            newp[(size_t)(b * Mpts) * 3 + 0] = x0;
            newp[(size_t)(b * Mpts) * 3 + 1] = y0;
            newp[(size_t)(b * Mpts) * 3 + 2] = z0;
        }
        __syncthreads();

        for (int m = 1; m < Mpts; m++) {
            // center chosen at m-1 (broadcast LDS)
            const float4 c = scen;
            const float cx = c.x, cy = c.y, cz = c.z;

            // ---- warp-uniform thin skip test ----
            float gx = fmaxf(fmaxf(wlox - cx, cx - whix), 0.f);
            float gy = fmaxf(fmaxf(wloy - cy, cy - whiy), 0.f);
            float gz = fmaxf(fmaxf(wloz - cz, cz - whiz), 0.f);
            float d2m = gx * gx + gy * gy + gz * gz;
            if (!(d2m * 0.99f >= __uint_as_float(wmaxc))) {
                // ---- packed exact-rn update of my 8 distances ----
                ull ncx = pack2(-cx, -cx), ncy = pack2(-cy, -cy), ncz = pack2(-cz, -cz);
#pragma unroll
                for (int pr = 0; pr < 4; pr++) {
                    ull dx = add2(PX[pr], ncx);
                    ull dy = add2(PY[pr], ncy);
                    ull dz = add2(PZ[pr], ncz);
                    ull d2 = add2(add2(mul2(dx, dx), mul2(dy, dy)), mul2(dz, dz));
                    uint lo, hi; unpack2(d2, lo, hi);
                    uint a = D[2 * pr];       D[2 * pr]     = (lo < a) ? lo : a;
                    uint cc2 = D[2 * pr + 1]; D[2 * pr + 1] = (hi < cc2) ? hi : cc2;
                }
                // per-thread argmax scan, original-index tie-break from sp4.w
                uint bd = 0, bg = 0; int bk = 0;
#pragma unroll
                for (int k = 0; k < 8; k++) {
                    uint gi = *(const uint*)((const char*)sp4
                                             + ((size_t)(k * 1024 + t) * 16u + 12u));
                    uint nw = D[k];
                    bool better = (k == 0) || (nw > bd) || (nw == bd && gi < bg);
                    if (better) { bd = nw; bg = gi; bk = k; }
                }
                // warp argmax + refresh persistent per-warp entries
                uint wmax = redux_max_u32(bd);
                uint cand = (bd == wmax) ? bg : 0xffffffffu;
                uint widx = redux_min_u32(cand);
                if (bd == wmax && bg == widx) {           // unique owner lane
                    swc[wrp] = sp4[bk * 1024 + t];
                }
                if (lane == 0) { swv[wrp] = wmax; swi[wrp] = widx; }
                wmaxc = wmax;
            }
            __syncthreads();                              // BAR_a

            if (wrp == 0) {
                uint v  = swv[lane];
                uint ii = swi[lane];
                uint gm = redux_max_u32(v);
                uint c2 = (v == gm) ? ii : 0xffffffffu;
                uint bi = redux_min_u32(c2);
                uint wm = __ballot_sync(FULLMASK, c2 == bi);  // v==gm && ii==bi
                int  wwin = __ffs(wm) - 1;                    // uniform
                float4 cc = swc[wwin];                        // broadcast LDS.128
                if (lane == 0) {
                    scen = make_float4(cc.x, cc.y, cc.z, 0.f);
                    g_idx[b * Mpts + m] = (int)bi;
                    float* o = newp + (size_t)(b * Mpts + m) * 3;
                    o[0] = cc.x; o[1] = cc.y; o[2] = cc.z;
                }
            }
            __syncthreads();                              // BAR_b
        }
    } else {
        // ------------------- conv1: f1t[b][n][c] = W @ f + bias ----------
        const int bc = blockIdx.x - Bsz;
        const int b  = bc >> 7;                 // 128 x-tiles per batch
        const int x0 = (bc & 127) * 64;
        const int t  = threadIdx.x;
        const int tx = t & 31;                  // c = tx + 32k
        const int ty = t >> 5;                  // x = x0 + ty*2 + e
        const float* fb = f + (size_t)b * CIN * Npts;

        float acc[2][8];
#pragma unroll
        for (int e = 0; e < 2; e++)
#pragma unroll
            for (int k = 0; k < 8; k++) acc[e][k] = 0.f;

        for (int cic = 0; cic < CIN; cic += 32) {
#pragma unroll
            for (int e = 0; e < 2; e++) {
                int lin = e * 1024 + t;
                int ci = lin >> 6, xl = lin & 63;
                sA[ci * 64 + xl] = fb[(size_t)(cic + ci) * Npts + x0 + xl];
            }
#pragma unroll
            for (int e = 0; e < 8; e++) {
                int lin = e * 1024 + t;
                int c = lin >> 5, ci = lin & 31;
                sW[ci * 257 + c] = w[c * CIN + cic + ci];
            }
            __syncthreads();
#pragma unroll
            for (int ci = 0; ci < 32; ci++) {
                float a0 = sA[ci * 64 + ty * 2];
                float a1 = sA[ci * 64 + ty * 2 + 1];
#pragma unroll
                for (int k = 0; k < 8; k++) {
                    float wv = sW[ci * 257 + tx + 32 * k];
                    acc[0][k] = fmaf(a0, wv, acc[0][k]);
                    acc[1][k] = fmaf(a1, wv, acc[1][k]);
                }
            }
            __syncthreads();
        }
#pragma unroll
        for (int e = 0; e < 2; e++) {
            int x = x0 + ty * 2 + e;
            float* orow = g_f1t + (size_t)(b * Npts + x) * COUT;
#pragma unroll
            for (int k = 0; k < 8; k++) {
                int c = tx + 32 * k;
                orow[c] = acc[e][k] + bias[c];
            }
        }
    }
}

// ============================================================================
// Kernel B: blocks x<128: ball query + dpn + theta + tmax (warp per center);
//           blocks x>=128: gather fi[b][ci][m] = f[b][ci][idx[b][m]].
// ============================================================================
#define BALLQ_SMEM ((3 * Npts + 3 * NDIR + 16 * KNB) * 4)

__global__ __launch_bounds__(512)
void ballq_gather_kernel(const float* __restrict__ p,
                         const float* __restrict__ newp,
                         const float* __restrict__ dirs,
                         const float* __restrict__ f)
{
    extern __shared__ float sh[];
    const int b = blockIdx.y;
    const int t = threadIdx.x;

    if (blockIdx.x >= Mpts / 16) {
        // ---------------- gather fi ----------------
        const int ci = blockIdx.x - Mpts / 16;
        const float* fb = f + (size_t)(b * CIN + ci) * Npts;
        float* ob = g_fi + (size_t)(b * CIN + ci) * Mpts;
        const int* ib = g_idx + b * Mpts;
        for (int m = t; m < Mpts; m += 512)
            ob[m] = fb[ib[m]];
        return;
    }

    float* spx = sh;
    float* spy = sh + Npts;
    float* spz = sh + 2 * Npts;
    float* sdx = sh + 3 * Npts;
    float* sdy = sdx + NDIR;
    float* sdz = sdy + NDIR;
    int*   sq  = (int*)(sdz + NDIR);

    const int w = t >> 5, lane = t & 31;
    const float* pb = p + (size_t)b * Npts * 3;

    for (int n = t; n < Npts; n += 512) {
        spx[n] = pb[3 * n];
        spy[n] = pb[3 * n + 1];
        spz[n] = pb[3 * n + 2];
    }
    if (t < NDIR) {
        float dx = dirs[3 * t], dy = dirs[3 * t + 1], dz = dirs[3 * t + 2];
        float nm = sqrtf(dx * dx + dy * dy + dz * dz);
        float inv = 1.0f / fmaxf(nm, 1e-12f);
        sdx[t] = dx * inv; sdy[t] = dy * inv; sdz[t] = dz * inv;
    }
    __syncthreads();

    const int m = blockIdx.x * 16 + w;
    const float* cp = newp + (size_t)(b * Mpts + m) * 3;
    const float cx = cp[0], cy = cp[1], cz = cp[2];

    int cnt = 0;
    int* q = sq + w * KNB;
    for (int ch = 0; ch < Npts / 32; ch++) {
        int n = ch * 32 + lane;
        float dx = spx[n] - cx, dy = spy[n] - cy, dz = spz[n] - cz;
        float d2 = dist2_exact(dx, dy, dz);
        bool pred = d2 < BQ_R2;
        unsigned mask = __ballot_sync(FULLMASK, pred);
        if (pred) {
            int pos = cnt + __popc(mask & ((1u << lane) - 1u));
            if (pos < KNB) q[pos] = n;
        }
        cnt += __popc(mask);
        if (cnt >= KNB) break;
    }
    __syncwarp();
    int eff = cnt < KNB ? cnt : KNB;
    int myn = q[lane < eff ? lane : 0];
    g_qidx[(b * Mpts + m) * KNB + lane] = myn;

    float dx = spx[myn] - cx, dy = spy[myn] - cy, dz = spz[myn] - cz;
    float nm = sqrtf(dx * dx + dy * dy + dz * dz);
    float inv = 1.0f / fmaxf(nm, 1e-12f);
    float ux = dx * inv, uy = dy * inv, uz = dz * inv;

    float mytm = 0.f;
#pragma unroll
    for (int d = 0; d < NDIR; d++) {
        float th = ux * sdx[d] + uy * sdy[d] + uz * sdz[d];
#pragma unroll
        for (int off = 16; off > 0; off >>= 1)
            th = fmaxf(th, __shfl_xor_sync(FULLMASK, th, off));
        if (lane == d) mytm = th;
    }
    g_tmax[((size_t)b * NDIR + lane) * Mpts + m] = mytm;
}

// ============================================================================
// Shared GEMM body: out[b][c][x] = sum_ci W[c][ci]*A[b][ci][x] (+epilogue)
// mode 0: identity  (A=g_fi,   out=outf, write acc+bias)
// mode 1: h         (A=g_tmax, out=g_h,  bn + exact gelu)
// mode 2: pe        (A=g_h,    out=outf, out += acc+bias)
// ============================================================================
__device__ __forceinline__
void gemm_body(const float* __restrict__ W, const float* __restrict__ bias,
               const float* __restrict__ bg, const float* __restrict__ bb,
               const float* __restrict__ bm, const float* __restrict__ bvv,
               float* __restrict__ outf, int Cin, int Cout, int mode, int co0,
               float* sA, float* sW)
{
    const int b = blockIdx.z;
    const int m0 = blockIdx.x * 64;
    const int t = threadIdx.x, tx = t & 15, ty = t >> 4;

    const float* A = (mode == 0) ? g_fi : (mode == 1 ? g_tmax : g_h);
    float* out = (mode == 1) ? g_h : outf;
    const float* Ab = A + (size_t)b * Cin * Mpts;

    float acc[4][4];
#pragma unroll
    for (int j = 0; j < 4; j++)
#pragma unroll
        for (int i = 0; i < 4; i++) acc[j][i] = 0.f;

    for (int cic = 0; cic < Cin; cic += 32) {
#pragma unroll
        for (int e = 0; e < 8; e++) {
            int lin = e * 256 + t;
            int ci = lin >> 6, xl = lin & 63;
            sA[ci * 64 + xl] = Ab[(size_t)(cic + ci) * Mpts + m0 + xl];
            int co = lin >> 5, ci2 = lin & 31;
            sW[co * 33 + ci2] = W[(size_t)(co0 + co) * Cin + cic + ci2];
        }
        __syncthreads();
#pragma unroll
        for (int ci = 0; ci < 32; ci++) {
            float4 a = *(const float4*)&sA[ci * 64 + tx * 4];
#pragma unroll
            for (int j = 0; j < 4; j++) {
                float wv = sW[(ty * 4 + j) * 33 + ci];
                acc[j][0] = fmaf(wv, a.x, acc[j][0]);
                acc[j][1] = fmaf(wv, a.y, acc[j][1]);
                acc[j][2] = fmaf(wv, a.z, acc[j][2]);
                acc[j][3] = fmaf(wv, a.w, acc[j][3]);
            }
        }
        __syncthreads();
    }

#pragma unroll
    for (int j = 0; j < 4; j++) {
        int c = co0 + ty * 4 + j;
        size_t o = ((size_t)b * Cout + c) * Mpts + m0 + tx * 4;
        float r[4] = {acc[j][0], acc[j][1], acc[j][2], acc[j][3]};
        if (mode == 0) {
            float bc = bias[c];
            float4 v = make_float4(r[0] + bc, r[1] + bc, r[2] + bc, r[3] + bc);
            *(float4*)&out[o] = v;
        } else if (mode == 1) {
            float scale = bg[c] / sqrtf(bvv[c] + BNEPS);
            float mean = bm[c], off = bb[c];
            float4 v;
            float* pv = &v.x;
#pragma unroll
            for (int i = 0; i < 4; i++) {
                float y = (r[i] - mean) * scale + off;
                pv[i] = 0.5f * y * (1.0f + erff(y * 0.70710678118654752f));
            }
            *(float4*)&out[o] = v;
        } else {
            float bc = bias[c];
            float4 old = *(const float4*)&out[o];
            float4 v = make_float4(old.x + r[0] + bc, old.y + r[1] + bc,
                                   old.z + r[2] + bc, old.w + r[3] + bc);
            *(float4*)&out[o] = v;
        }
    }
}

// Combined identity (mode 0, y in [0,4)) + h (mode 1, y in [4,6)) launch.
__global__ __launch_bounds__(256)
void gemm01_kernel(const float* __restrict__ skip_w, const float* __restrict__ skip_b,
                   const float* __restrict__ de_w1,
                   const float* __restrict__ de_g, const float* __restrict__ de_bb,
                   const float* __restrict__ de_m, const float* __restrict__ de_v,
                   float* __restrict__ outf)
{
    __shared__ float sA[32 * 64];
    __shared__ float sW[64 * 33];
    if (blockIdx.y < COUT / 64) {
        gemm_body(skip_w, skip_b, nullptr, nullptr, nullptr, nullptr,
                  outf, CIN, COUT, 0, blockIdx.y * 64, sA, sW);
    } else {
        gemm_body(de_w1, nullptr, de_g, de_bb, de_m, de_v,
                  outf, NDIR, HALF, 1, (blockIdx.y - COUT / 64) * 64, sA, sW);
    }
}

// pe GEMM (mode 2)
__global__ __launch_bounds__(256)
void gemm2_kernel(const float* __restrict__ de_w2, const float* __restrict__ de_b2,
                  float* __restrict__ outf)
{
    __shared__ float sA[32 * 64];
    __shared__ float sW[64 * 33];
    gemm_body(de_w2, de_b2, nullptr, nullptr, nullptr, nullptr,
              outf, HALF, COUT, 2, blockIdx.y * 64, sA, sW);
}

// ============================================================================
// Kernel E: fj gather-max over K + bn1, += into outf. Warp per center m.
// ============================================================================
__global__ __launch_bounds__(1024)
void fjmax_kernel(const float* __restrict__ bg, const float* __restrict__ bb,
                  const float* __restrict__ bm, const float* __restrict__ bvv,
                  float* __restrict__ outf)
{
    __shared__ float st[COUT * 33];
    const int b = blockIdx.y, m0 = blockIdx.x * 32;
    const int t = threadIdx.x, w = t >> 5, lane = t & 31;
    const int m = m0 + w;

    int kn = g_qidx[(b * Mpts + m) * KNB + lane];
    int first = __shfl_sync(FULLMASK, kn, 0);

    float4 a0 = make_float4(-3.4e38f, -3.4e38f, -3.4e38f, -3.4e38f);
    float4 a1 = a0;
    for (int k = 0; k < KNB; k++) {
        int n = __shfl_sync(FULLMASK, kn, k);
        if (k > 0 && n == first) continue;   // uniform across warp
        const float4* row = (const float4*)(g_f1t + (size_t)(b * Npts + n) * COUT);
        float4 v0 = row[lane];
        float4 v1 = row[32 + lane];
        a0.x = fmaxf(a0.x, v0.x); a0.y = fmaxf(a0.y, v0.y);
        a0.z = fmaxf(a0.z, v0.z); a0.w = fmaxf(a0.w, v0.w);
        a1.x = fmaxf(a1.x, v1.x); a1.y = fmaxf(a1.y, v1.y);
        a1.z = fmaxf(a1.z, v1.z); a1.w = fmaxf(a1.w, v1.w);
    }
    const float* pa0 = &a0.x;
    const float* pa1 = &a1.x;
#pragma unroll
    for (int j = 0; j < 4; j++) {
        st[(lane * 4 + j) * 33 + w] = pa0[j];
        st[(128 + lane * 4 + j) * 33 + w] = pa1[j];
    }
    __syncthreads();

    const int c = t >> 2, part = t & 3;
    float scale = bg[c] / sqrtf(bvv[c] + BNEPS);
    float mean = bm[c], off = bb[c];
    float* o = outf + ((size_t)b * COUT + c) * Mpts + m0 + part * 8;
#pragma unroll
    for (int i = 0; i < 8; i++) {
        float x = st[c * 33 + part * 8 + i];
        o[i] += (x - mean) * scale + off;
    }
}

// ============================================================================
extern "C" void kernel_launch(void* const* d_in, const int* in_sizes, int n_in,
                              void* d_out, int out_size)
{
    const float* p       = (const float*)d_in[0];
    const float* f       = (const float*)d_in[1];
    const float* conv1_w = (const float*)d_in[2];
    const float* conv1_b = (const float*)d_in[3];
    const float* skip_w  = (const float*)d_in[4];
    const float* skip_b  = (const float*)d_in[5];
    const float* bn1_g   = (const float*)d_in[6];
    const float* bn1_b   = (const float*)d_in[7];
    const float* bn1_m   = (const float*)d_in[8];
    const float* bn1_v   = (const float*)d_in[9];
    const float* dirs    = (const float*)d_in[10];
    const float* de_w1   = (const float*)d_in[11];
    const float* de_g    = (const float*)d_in[12];
    const float* de_bb   = (const float*)d_in[13];
    const float* de_m    = (const float*)d_in[14];
    const float* de_v    = (const float*)d_in[15];
    const float* de_w2   = (const float*)d_in[16];
    const float* de_b2   = (const float*)d_in[17];

    float* outp = (float*)d_out;                 // new_p (B,M,3)
    float* outf = outp + Bsz * Mpts * 3;         // f_out (B,256,M)

    cudaFuncSetAttribute(fps_conv1_kernel,
                         cudaFuncAttributeMaxDynamicSharedMemorySize, FPS_DYN);
    cudaFuncSetAttribute(ballq_gather_kernel,
                         cudaFuncAttributeMaxDynamicSharedMemorySize, BALLQ_SMEM);

    // 1) FPS (4 blocks, thin-skip + warp0 combine) + conv1 GEMM (512 blocks)
    fps_conv1_kernel<<<Bsz + Bsz * 128, 1024, FPS_DYN>>>(p, f, conv1_w, conv1_b, outp);
    // 2) ball query + theta + tmax  ||  gather fi   (one launch)
    ballq_gather_kernel<<<dim3(Mpts / 16 + CIN, Bsz), 512, BALLQ_SMEM>>>(
        p, outp, dirs, f);
    // 3) identity -> outf (write)  ||  h = gelu(bn(de_w1 @ tmax)) -> g_h
    gemm01_kernel<<<dim3(Mpts / 64, COUT / 64 + HALF / 64, Bsz), 256>>>(
        skip_w, skip_b, de_w1, de_g, de_bb, de_m, de_v, outf);
    // 4) pe: outf += de_w2 @ h + de_b2
    gemm2_kernel<<<dim3(Mpts / 64, COUT / 64, Bsz), 256>>>(de_w2, de_b2, outf);
    // 5) outf += bn1(max_k fj)
    fjmax_kernel<<<dim3(Mpts / 32, Bsz), 1024>>>(bn1_g, bn1_b, bn1_m, bn1_v, outf);
}

// round 16
// speedup vs baseline: 1.1066x; 1.0011x over previous
#include <cuda_runtime.h>
#include <math.h>

#define Bsz   4
#define Npts  8192
#define Mpts  2048
#define CIN   128
#define COUT  256
#define KNB   32
#define NDIR  32
#define HALF  128
#define BNEPS 1e-5f
#define BQ_R2 0.01f
#define FULLMASK 0xffffffffu

// FPS dyn smem: sp4 (N float4, [k][t] layout, .w = original index) + hist(513)
#define FPS_DYN (Npts * 16 + 513 * 4)

typedef unsigned long long ull;
typedef unsigned int uint;

// ---------------- scratch (device globals; no runtime allocation) ----------
__device__ int   g_idx [Bsz * Mpts];
__device__ float g_fi  [(size_t)Bsz * CIN * Mpts];     // (B, Cin, M)
__device__ float g_f1t [(size_t)Bsz * Npts * COUT];    // (B, N, Cout) n-major
__device__ int   g_qidx[Bsz * Mpts * KNB];
__device__ float g_tmax[(size_t)Bsz * NDIR * Mpts];    // (B, D, M)
__device__ float g_h   [(size_t)Bsz * HALF * Mpts];    // (B, 128, M)
__device__ float g_bn  [(size_t)Bsz * COUT * Mpts];    // bn1(max fj) scratch

// exact XLA-style distance: ((dx*dx + dy*dy) + dz*dz), rn, no FMA contraction
__device__ __forceinline__ float dist2_exact(float dx, float dy, float dz) {
    return __fadd_rn(__fadd_rn(__fmul_rn(dx, dx), __fmul_rn(dy, dy)),
                     __fmul_rn(dz, dz));
}

// ---------------- f32x2 packed helpers (exact per-element rn) --------------
__device__ __forceinline__ ull pack2(float lo, float hi) {
    ull r; asm("mov.b64 %0, {%1, %2};" : "=l"(r) : "f"(lo), "f"(hi)); return r;
}
__device__ __forceinline__ void unpack2(ull v, uint& lo, uint& hi) {
    asm("mov.b64 {%0, %1}, %2;" : "=r"(lo), "=r"(hi) : "l"(v));
}
__device__ __forceinline__ ull add2(ull a, ull b) {
    ull r; asm("add.rn.f32x2 %0, %1, %2;" : "=l"(r) : "l"(a), "l"(b)); return r;
}
__device__ __forceinline__ ull mul2(ull a, ull b) {
    ull r; asm("mul.rn.f32x2 %0, %1, %2;" : "=l"(r) : "l"(a), "l"(b)); return r;
}
__device__ __forceinline__ uint redux_max_u32(uint v) {
    uint r; asm("redux.sync.max.u32 %0, %1, 0xffffffff;" : "=r"(r) : "r"(v)); return r;
}
__device__ __forceinline__ uint redux_min_u32(uint v) {
    uint r; asm("redux.sync.min.u32 %0, %1, 0xffffffff;" : "=r"(r) : "r"(v)); return r;
}

// ============================================================================
// Kernel A: blocks 0..3 = FPS (one CTA/batch; thin-skip + warp0 combine);
//           blocks 4..  = conv1 GEMM (runs in FPS's shadow).
// ============================================================================
__global__ __launch_bounds__(1024, 1)
void fps_conv1_kernel(const float* __restrict__ p,
                      const float* __restrict__ f,
                      const float* __restrict__ w,      // conv1_w (256,128)
                      const float* __restrict__ bias,   // conv1_b (256)
                      float* __restrict__ newp)         // d_out head (B,M,3)
{
    extern __shared__ char dsm[];
    __shared__ float sA[32 * 64];      // conv1 only
    __shared__ float sW[32 * 257];     // conv1 only
    __shared__ uint   swv[32];         // FPS: per-warp max bits (persistent)
    __shared__ uint   swi[32];         // FPS: per-warp argmax orig index
    __shared__ float4 swc[32];         // FPS: per-warp winner coords
    __shared__ float4 scen;            // FPS: current center (x,y,z,idx)

    if (blockIdx.x < Bsz) {
        // ----------------------------- FPS -------------------------------
        float4* sp4  = (float4*)dsm;                   // [k][t]: k*1024+t
        uint*   hist = (uint*)(dsm + Npts * 16);       // 513

        const int b = blockIdx.x;
        const float* pb = p + (size_t)b * Npts * 3;
        const int t = threadIdx.x, lane = t & 31, wrp = t >> 5;

        // ---- preamble: counting-sort into 512 MORTON-ordered bins ----
        if (t < 512) hist[t] = 0;
        __syncthreads();
        {
            float lx[8], ly[8], lz[8];
            uint  lb[8];
#pragma unroll
            for (int k = 0; k < 8; k++) {
                int i = k * 1024 + t;
                lx[k] = pb[3 * i];
                ly[k] = pb[3 * i + 1];
                lz[k] = pb[3 * i + 2];
                uint bx = (uint)(int)fminf(fmaxf(lx[k], 0.f) * 8.f, 7.f);
                uint by = (uint)(int)fminf(fmaxf(ly[k], 0.f) * 8.f, 7.f);
                uint bz = (uint)(int)fminf(fmaxf(lz[k], 0.f) * 8.f, 7.f);
                lb[k] = ((bx & 4u) << 6) | ((bx & 2u) << 4) | ((bx & 1u) << 2)
                      | ((by & 4u) << 5) | ((by & 2u) << 3) | ((by & 1u) << 1)
                      | ((bz & 4u) << 4) | ((bz & 2u) << 2) |  (bz & 1u);
                atomicAdd(&hist[lb[k]], 1u);
            }
            __syncthreads();
            if (t == 0) {                  // serial exclusive scan (once)
                uint run = 0;
                for (int j = 0; j < 512; j++) {
                    uint c = hist[j]; hist[j] = run; run += c;
                }
            }
            __syncthreads();
#pragma unroll
            for (int k = 0; k < 8; k++) {
                uint pos = atomicAdd(&hist[lb[k]], 1u);
                uint dst = (pos & 7u) * 1024u + (pos >> 3);   // [k][t] layout
                sp4[dst] = make_float4(lx[k], ly[k], lz[k],
                                       __uint_as_float((uint)(k * 1024 + t)));
            }
        }
        __syncthreads();

        // ---- load my 8 sorted points into packed registers + warp bbox ----
        ull PX[4], PY[4], PZ[4];
        uint D[8];
        float wlox, whix, wloy, whiy, wloz, whiz;
        {
            float qx[8], qy[8], qz[8];
#pragma unroll
            for (int k = 0; k < 8; k++) {
                float4 q = sp4[k * 1024 + t];        // conflict-free
                qx[k] = q.x; qy[k] = q.y; qz[k] = q.z;
                D[k] = __float_as_uint(1e10f);
            }
#pragma unroll
            for (int j = 0; j < 4; j++) {
                PX[j] = pack2(qx[2 * j], qx[2 * j + 1]);
                PY[j] = pack2(qy[2 * j], qy[2 * j + 1]);
                PZ[j] = pack2(qz[2 * j], qz[2 * j + 1]);
            }
            float alox = qx[0], ahix = qx[0], aloy = qy[0], ahiy = qy[0];
            float aloz = qz[0], ahiz = qz[0];
#pragma unroll
            for (int k = 1; k < 8; k++) {
                alox = fminf(alox, qx[k]); ahix = fmaxf(ahix, qx[k]);
                aloy = fminf(aloy, qy[k]); ahiy = fmaxf(ahiy, qy[k]);
                aloz = fminf(aloz, qz[k]); ahiz = fmaxf(ahiz, qz[k]);
            }
#pragma unroll
            for (int off = 16; off > 0; off >>= 1) {
                alox = fminf(alox, __shfl_xor_sync(FULLMASK, alox, off));
                ahix = fmaxf(ahix, __shfl_xor_sync(FULLMASK, ahix, off));
                aloy = fminf(aloy, __shfl_xor_sync(FULLMASK, aloy, off));
                ahiy = fmaxf(ahiy, __shfl_xor_sync(FULLMASK, ahiy, off));
                aloz = fminf(aloz, __shfl_xor_sync(FULLMASK, aloz, off));
                ahiz = fmaxf(ahiz, __shfl_xor_sync(FULLMASK, ahiz, off));
            }
            wlox = alox; whix = ahix; wloy = aloy; whiy = ahiy;
            wloz = aloz; whiz = ahiz;
        }

        uint wmaxc = __float_as_uint(1e10f);   // this warp's own cached max

        if (t == 0) {
            float x0 = __ldg(&pb[0]), y0 = __ldg(&pb[1]), z0 = __ldg(&pb[2]);
            scen = make_float4(x0, y0, z0, 0.f);
            g_idx[b * Mpts] = 0;
            newp[(size_t)(b * Mpts) * 3 + 0] = x0;
            newp[(size_t)(b * Mpts) * 3 + 1] = y0;
            newp[(size_t)(b * Mpts) * 3 + 2] = z0;
        }
        __syncthreads();

        for (int m = 1; m < Mpts; m++) {
            // center chosen at m-1 (broadcast LDS)
            const float4 c = scen;
            const float cx = c.x, cy = c.y, cz = c.z;

            // ---- warp-uniform thin skip test ----
            float gx = fmaxf(fmaxf(wlox - cx, cx - whix), 0.f);
            float gy = fmaxf(fmaxf(wloy - cy, cy - whiy), 0.f);
            float gz = fmaxf(fmaxf(wloz - cz, cz - whiz), 0.f);
            float d2m = gx * gx + gy * gy + gz * gz;
            if (!(d2m * 0.99f >= __uint_as_float(wmaxc))) {
                // ---- packed exact-rn update of my 8 distances ----
                ull ncx = pack2(-cx, -cx), ncy = pack2(-cy, -cy), ncz = pack2(-cz, -cz);
#pragma unroll
                for (int pr = 0; pr < 4; pr++) {
                    ull dx = add2(PX[pr], ncx);
                    ull dy = add2(PY[pr], ncy);
                    ull dz = add2(PZ[pr], ncz);
                    ull d2 = add2(add2(mul2(dx, dx), mul2(dy, dy)), mul2(dz, dz));
                    uint lo, hi; unpack2(d2, lo, hi);
                    uint a = D[2 * pr];       D[2 * pr]     = (lo < a) ? lo : a;
                    uint cc2 = D[2 * pr + 1]; D[2 * pr + 1] = (hi < cc2) ? hi : cc2;
                }
                // per-thread argmax scan, original-index tie-break from sp4.w
                uint bd = 0, bg = 0; int bk = 0;
#pragma unroll
                for (int k = 0; k < 8; k++) {
                    uint gi = *(const uint*)((const char*)sp4
                                             + ((size_t)(k * 1024 + t) * 16u + 12u));
                    uint nw = D[k];
                    bool better = (k == 0) || (nw > bd) || (nw == bd && gi < bg);
                    if (better) { bd = nw; bg = gi; bk = k; }
                }
                // warp argmax + refresh persistent per-warp entries
                uint wmax = redux_max_u32(bd);
                uint cand = (bd == wmax) ? bg : 0xffffffffu;
                uint widx = redux_min_u32(cand);
                if (bd == wmax && bg == widx) {           // unique owner lane
                    swc[wrp] = sp4[bk * 1024 + t];
                }
                if (lane == 0) { swv[wrp] = wmax; swi[wrp] = widx; }
                wmaxc = wmax;
            }
            __syncthreads();                              // BAR_a

            if (wrp == 0) {
                uint v  = swv[lane];
                uint ii = swi[lane];
                uint gm = redux_max_u32(v);
                uint c2 = (v == gm) ? ii : 0xffffffffu;
                uint bi = redux_min_u32(c2);
                uint wm = __ballot_sync(FULLMASK, c2 == bi);  // v==gm && ii==bi
                int  wwin = __ffs(wm) - 1;                    // uniform
                float4 cc = swc[wwin];                        // broadcast LDS.128
                if (lane == 0) {
                    scen = make_float4(cc.x, cc.y, cc.z, 0.f);
                    g_idx[b * Mpts + m] = (int)bi;
                    float* o = newp + (size_t)(b * Mpts + m) * 3;
                    o[0] = cc.x; o[1] = cc.y; o[2] = cc.z;
                }
            }
            __syncthreads();                              // BAR_b
        }
    } else {
        // ------------------- conv1: f1t[b][n][c] = W @ f + bias ----------
        const int bc = blockIdx.x - Bsz;
        const int b  = bc >> 7;                 // 128 x-tiles per batch
        const int x0 = (bc & 127) * 64;
        const int t  = threadIdx.x;
        const int tx = t & 31;                  // c = tx + 32k
        const int ty = t >> 5;                  // x = x0 + ty*2 + e
        const float* fb = f + (size_t)b * CIN * Npts;

        float acc[2][8];
#pragma unroll
        for (int e = 0; e < 2; e++)
#pragma unroll
            for (int k = 0; k < 8; k++) acc[e][k] = 0.f;

        for (int cic = 0; cic < CIN; cic += 32) {
#pragma unroll
            for (int e = 0; e < 2; e++) {
                int lin = e * 1024 + t;
                int ci = lin >> 6, xl = lin & 63;
                sA[ci * 64 + xl] = fb[(size_t)(cic + ci) * Npts + x0 + xl];
            }
#pragma unroll
            for (int e = 0; e < 8; e++) {
                int lin = e * 1024 + t;
                int c = lin >> 5, ci = lin & 31;
                sW[ci * 257 + c] = w[c * CIN + cic + ci];
            }
            __syncthreads();
#pragma unroll
            for (int ci = 0; ci < 32; ci++) {
                float a0 = sA[ci * 64 + ty * 2];
                float a1 = sA[ci * 64 + ty * 2 + 1];
#pragma unroll
                for (int k = 0; k < 8; k++) {
                    float wv = sW[ci * 257 + tx + 32 * k];
                    acc[0][k] = fmaf(a0, wv, acc[0][k]);
                    acc[1][k] = fmaf(a1, wv, acc[1][k]);
                }
            }
            __syncthreads();
        }
#pragma unroll
        for (int e = 0; e < 2; e++) {
            int x = x0 + ty * 2 + e;
            float* orow = g_f1t + (size_t)(b * Npts + x) * COUT;
#pragma unroll
            for (int k = 0; k < 8; k++) {
                int c = tx + 32 * k;
                orow[c] = acc[e][k] + bias[c];
            }
        }
    }
}

// ============================================================================
// Kernel B: blocks x<128: ball query + dpn + theta + tmax (warp per center);
//           blocks x>=128: gather fi[b][ci][m] = f[b][ci][idx[b][m]].
// ============================================================================
#define BALLQ_SMEM ((3 * Npts + 3 * NDIR + 16 * KNB) * 4)

__global__ __launch_bounds__(512)
void ballq_gather_kernel(const float* __restrict__ p,
                         const float* __restrict__ newp,
                         const float* __restrict__ dirs,
                         const float* __restrict__ f)
{
    extern __shared__ float sh[];
    const int b = blockIdx.y;
    const int t = threadIdx.x;

    if (blockIdx.x >= Mpts / 16) {
        // ---------------- gather fi ----------------
        const int ci = blockIdx.x - Mpts / 16;
        const float* fb = f + (size_t)(b * CIN + ci) * Npts;
        float* ob = g_fi + (size_t)(b * CIN + ci) * Mpts;
        const int* ib = g_idx + b * Mpts;
        for (int m = t; m < Mpts; m += 512)
            ob[m] = fb[ib[m]];
        return;
    }

    float* spx = sh;
    float* spy = sh + Npts;
    float* spz = sh + 2 * Npts;
    float* sdx = sh + 3 * Npts;
    float* sdy = sdx + NDIR;
    float* sdz = sdy + NDIR;
    int*   sq  = (int*)(sdz + NDIR);

    const int w = t >> 5, lane = t & 31;
    const float* pb = p + (size_t)b * Npts * 3;

    for (int n = t; n < Npts; n += 512) {
        spx[n] = pb[3 * n];
        spy[n] = pb[3 * n + 1];
        spz[n] = pb[3 * n + 2];
    }
    if (t < NDIR) {
        float dx = dirs[3 * t], dy = dirs[3 * t + 1], dz = dirs[3 * t + 2];
        float nm = sqrtf(dx * dx + dy * dy + dz * dz);
        float inv = 1.0f / fmaxf(nm, 1e-12f);
        sdx[t] = dx * inv; sdy[t] = dy * inv; sdz[t] = dz * inv;
    }
    __syncthreads();

    const int m = blockIdx.x * 16 + w;
    const float* cp = newp + (size_t)(b * Mpts + m) * 3;
    const float cx = cp[0], cy = cp[1], cz = cp[2];

    int cnt = 0;
    int* q = sq + w * KNB;
    for (int ch = 0; ch < Npts / 32; ch++) {
        int n = ch * 32 + lane;
        float dx = spx[n] - cx, dy = spy[n] - cy, dz = spz[n] - cz;
        float d2 = dist2_exact(dx, dy, dz);
        bool pred = d2 < BQ_R2;
        unsigned mask = __ballot_sync(FULLMASK, pred);
        if (pred) {
            int pos = cnt + __popc(mask & ((1u << lane) - 1u));
            if (pos < KNB) q[pos] = n;
        }
        cnt += __popc(mask);
        if (cnt >= KNB) break;
    }
    __syncwarp();
    int eff = cnt < KNB ? cnt : KNB;
    int myn = q[lane < eff ? lane : 0];
    g_qidx[(b * Mpts + m) * KNB + lane] = myn;

    float dx = spx[myn] - cx, dy = spy[myn] - cy, dz = spz[myn] - cz;
    float nm = sqrtf(dx * dx + dy * dy + dz * dz);
    float inv = 1.0f / fmaxf(nm, 1e-12f);
    float ux = dx * inv, uy = dy * inv, uz = dz * inv;

    float mytm = 0.f;
#pragma unroll
    for (int d = 0; d < NDIR; d++) {
        float th = ux * sdx[d] + uy * sdy[d] + uz * sdz[d];
#pragma unroll
        for (int off = 16; off > 0; off >>= 1)
            th = fmaxf(th, __shfl_xor_sync(FULLMASK, th, off));
        if (lane == d) mytm = th;
    }
    g_tmax[((size_t)b * NDIR + lane) * Mpts + m] = mytm;
}

// ============================================================================
// Shared GEMM body: out[c][x] = sum_ci W[c][ci]*A[ci][x] (+epilogue)
// mode 0: identity  (A=g_fi,   out=outf, write acc+bias)
// mode 1: h         (A=g_tmax, out=g_h,  bn + exact gelu)
// mode 2: pe+final  (A=g_h,    out=outf, out = ((old+acc)+bias)+g_bn)
// ============================================================================
__device__ __forceinline__
void gemm_body(const float* __restrict__ W, const float* __restrict__ bias,
               const float* __restrict__ bg, const float* __restrict__ bb,
               const float* __restrict__ bm, const float* __restrict__ bvv,
               float* __restrict__ outf, int Cin, int Cout, int mode, int co0,
               int b, int m0, float* sA, float* sW)
{
    const int t = threadIdx.x, tx = t & 15, ty = t >> 4;

    const float* A = (mode == 0) ? g_fi : (mode == 1 ? g_tmax : g_h);
    float* out = (mode == 1) ? g_h : outf;
    const float* Ab = A + (size_t)b * Cin * Mpts;

    float acc[4][4];
#pragma unroll
    for (int j = 0; j < 4; j++)
#pragma unroll
        for (int i = 0; i < 4; i++) acc[j][i] = 0.f;

    for (int cic = 0; cic < Cin; cic += 32) {
#pragma unroll
        for (int e = 0; e < 8; e++) {
            int lin = e * 256 + t;
            int ci = lin >> 6, xl = lin & 63;
            sA[ci * 64 + xl] = Ab[(size_t)(cic + ci) * Mpts + m0 + xl];
            int co = lin >> 5, ci2 = lin & 31;
            sW[co * 33 + ci2] = W[(size_t)(co0 + co) * Cin + cic + ci2];
        }
        __syncthreads();
#pragma unroll
        for (int ci = 0; ci < 32; ci++) {
            float4 a = *(const float4*)&sA[ci * 64 + tx * 4];
#pragma unroll
            for (int j = 0; j < 4; j++) {
                float wv = sW[(ty * 4 + j) * 33 + ci];
                acc[j][0] = fmaf(wv, a.x, acc[j][0]);
                acc[j][1] = fmaf(wv, a.y, acc[j][1]);
                acc[j][2] = fmaf(wv, a.z, acc[j][2]);
                acc[j][3] = fmaf(wv, a.w, acc[j][3]);
            }
        }
        __syncthreads();
    }

#pragma unroll
    for (int j = 0; j < 4; j++) {
        int c = co0 + ty * 4 + j;
        size_t o = ((size_t)b * Cout + c) * Mpts + m0 + tx * 4;
        float r[4] = {acc[j][0], acc[j][1], acc[j][2], acc[j][3]};
        if (mode == 0) {
            float bc = bias[c];
            float4 v = make_float4(r[0] + bc, r[1] + bc, r[2] + bc, r[3] + bc);
            *(float4*)&out[o] = v;
        } else if (mode == 1) {
            float scale = bg[c] / sqrtf(bvv[c] + BNEPS);
            float mean = bm[c], off = bb[c];
            float4 v;
            float* pv = &v.x;
#pragma unroll
            for (int i = 0; i < 4; i++) {
                float y = (r[i] - mean) * scale + off;
                pv[i] = 0.5f * y * (1.0f + erff(y * 0.70710678118654752f));
            }
            *(float4*)&out[o] = v;
        } else {
            float bc = bias[c];
            float4 old = *(const float4*)&out[o];
            float4 bn = *(const float4*)&g_bn[o];
            // ((old + r) + bc) + bn  — identical order to previous 2-kernel sum
            float4 v = make_float4(((old.x + r[0]) + bc) + bn.x,
                                   ((old.y + r[1]) + bc) + bn.y,
                                   ((old.z + r[2]) + bc) + bn.z,
                                   ((old.w + r[3]) + bc) + bn.w);
            *(float4*)&out[o] = v;
        }
    }
}

// ============================================================================
// Kernel C: combined launch —
//   bx <  192: gemm01 (identity mode0 grp 0..3, h mode1 grp 4..5), m-tile bx%32
//   bx >= 192: fjmax -> g_bn (256 thr, warp per center, 8 centers/block)
// ============================================================================
__global__ __launch_bounds__(256)
void gemm01_fj_kernel(const float* __restrict__ skip_w, const float* __restrict__ skip_b,
                      const float* __restrict__ de_w1,
                      const float* __restrict__ de_g, const float* __restrict__ de_bb,
                      const float* __restrict__ de_m, const float* __restrict__ de_v,
                      const float* __restrict__ bg, const float* __restrict__ bb,
                      const float* __restrict__ bm, const float* __restrict__ bvv,
                      float* __restrict__ outf)
{
    __shared__ float sA[32 * 64];
    __shared__ float sW[64 * 33];
    __shared__ float st[COUT * 9];      // fjmax transpose (9-stride: read CF)
    const int b = blockIdx.y;
    const int bx = blockIdx.x;
    const int t = threadIdx.x;

    if (bx < 192) {
        const int m0 = (bx & 31) * 64;
        const int grp = bx >> 5;          // 0..5
        if (grp < COUT / 64) {
            gemm_body(skip_w, skip_b, nullptr, nullptr, nullptr, nullptr,
                      outf, CIN, COUT, 0, grp * 64, b, m0, sA, sW);
        } else {
            gemm_body(de_w1, nullptr, de_g, de_bb, de_m, de_v,
                      outf, NDIR, HALF, 1, (grp - COUT / 64) * 64, b, m0, sA, sW);
        }
        return;
    }

    // ---------------- fjmax -> g_bn ----------------
    const int m0 = (bx - 192) * 8;
    const int w = t >> 5, lane = t & 31;
    const int m = m0 + w;

    int kn = g_qidx[(b * Mpts + m) * KNB + lane];
    int first = __shfl_sync(FULLMASK, kn, 0);

    float4 a0 = make_float4(-3.4e38f, -3.4e38f, -3.4e38f, -3.4e38f);
    float4 a1 = a0;
    for (int k = 0; k < KNB; k++) {
        int n = __shfl_sync(FULLMASK, kn, k);
        if (k > 0 && n == first) continue;   // uniform across warp
        const float4* row = (const float4*)(g_f1t + (size_t)(b * Npts + n) * COUT);
        float4 v0 = row[lane];
        float4 v1 = row[32 + lane];
        a0.x = fmaxf(a0.x, v0.x); a0.y = fmaxf(a0.y, v0.y);
        a0.z = fmaxf(a0.z, v0.z); a0.w = fmaxf(a0.w, v0.w);
        a1.x = fmaxf(a1.x, v1.x); a1.y = fmaxf(a1.y, v1.y);
        a1.z = fmaxf(a1.z, v1.z); a1.w = fmaxf(a1.w, v1.w);
    }
    const float* pa0 = &a0.x;
    const float* pa1 = &a1.x;
#pragma unroll
    for (int j = 0; j < 4; j++) {
        st[(lane * 4 + j) * 9 + w] = pa0[j];
        st[(128 + lane * 4 + j) * 9 + w] = pa1[j];
    }
    __syncthreads();

    const int c = t;                     // 256 threads = 256 channels
    float scale = bg[c] / sqrtf(bvv[c] + BNEPS);
    float mean = bm[c], off = bb[c];
    float* ob = g_bn + ((size_t)b * COUT + c) * Mpts + m0;
#pragma unroll
    for (int i = 0; i < 8; i++)
        ob[i] = (st[c * 9 + i] - mean) * scale + off;
}

// pe+final GEMM (mode 2)
__global__ __launch_bounds__(256)
void gemm2_kernel(const float* __restrict__ de_w2, const float* __restrict__ de_b2,
                  float* __restrict__ outf)
{
    __shared__ float sA[32 * 64];
    __shared__ float sW[64 * 33];
    gemm_body(de_w2, de_b2, nullptr, nullptr, nullptr, nullptr,
              outf, HALF, COUT, 2, blockIdx.y * 64, blockIdx.z,
              blockIdx.x * 64, sA, sW);
}

// ============================================================================
extern "C" void kernel_launch(void* const* d_in, const int* in_sizes, int n_in,
                              void* d_out, int out_size)
{
    const float* p       = (const float*)d_in[0];
    const float* f       = (const float*)d_in[1];
    const float* conv1_w = (const float*)d_in[2];
    const float* conv1_b = (const float*)d_in[3];
    const float* skip_w  = (const float*)d_in[4];
    const float* skip_b  = (const float*)d_in[5];
    const float* bn1_g   = (const float*)d_in[6];
    const float* bn1_b   = (const float*)d_in[7];
    const float* bn1_m   = (const float*)d_in[8];
    const float* bn1_v   = (const float*)d_in[9];
    const float* dirs    = (const float*)d_in[10];
    const float* de_w1   = (const float*)d_in[11];
    const float* de_g    = (const float*)d_in[12];
    const float* de_bb   = (const float*)d_in[13];
    const float* de_m    = (const float*)d_in[14];
    const float* de_v    = (const float*)d_in[15];
    const float* de_w2   = (const float*)d_in[16];
    const float* de_b2   = (const float*)d_in[17];

    float* outp = (float*)d_out;                 // new_p (B,M,3)
    float* outf = outp + Bsz * Mpts * 3;         // f_out (B,256,M)

    cudaFuncSetAttribute(fps_conv1_kernel,
                         cudaFuncAttributeMaxDynamicSharedMemorySize, FPS_DYN);
    cudaFuncSetAttribute(ballq_gather_kernel,
                         cudaFuncAttributeMaxDynamicSharedMemorySize, BALLQ_SMEM);

    // 1) FPS (4 blocks) + conv1 GEMM (512 blocks)
    fps_conv1_kernel<<<Bsz + Bsz * 128, 1024, FPS_DYN>>>(p, f, conv1_w, conv1_b, outp);
    // 2) ball query + theta + tmax  ||  gather fi
    ballq_gather_kernel<<<dim3(Mpts / 16 + CIN, Bsz), 512, BALLQ_SMEM>>>(
        p, outp, dirs, f);
    // 3) identity -> outf  ||  h -> g_h  ||  fjmax -> g_bn   (one launch)
    gemm01_fj_kernel<<<dim3(192 + Mpts / 8, Bsz), 256>>>(
        skip_w, skip_b, de_w1, de_g, de_bb, de_m, de_v,
        bn1_g, bn1_b, bn1_m, bn1_v, outf);
    // 4) final: outf = identity + (de_w2 @ h + de_b2) + g_bn
    gemm2_kernel<<<dim3(Mpts / 64, COUT / 64, Bsz), 256>>>(de_w2, de_b2, outf);
}

// round 17
// speedup vs baseline: 1.1089x; 1.0021x over previous
#include <cuda_runtime.h>
#include <math.h>

#define Bsz   4
#define Npts  8192
#define Mpts  2048
#define CIN   128
#define COUT  256
#define KNB   32
#define NDIR  32
#define HALF  128
#define BNEPS 1e-5f
#define BQ_R2 0.01f
#define FULLMASK 0xffffffffu

// FPS dyn smem: sp4 (N float4, [k][t] layout, .w = original index) + hist(513)
#define FPS_DYN (Npts * 16 + 513 * 4)

typedef unsigned long long ull;
typedef unsigned int uint;

// ---------------- scratch (device globals; no runtime allocation) ----------
__device__ int   g_idx [Bsz * Mpts];
__device__ float g_fi  [(size_t)Bsz * CIN * Mpts];     // (B, Cin, M)
__device__ float g_f1t [(size_t)Bsz * Npts * COUT];    // (B, N, Cout) n-major
__device__ int   g_qidx[Bsz * Mpts * KNB];
__device__ float g_tmax[(size_t)Bsz * NDIR * Mpts];    // (B, D, M)
__device__ float g_h   [(size_t)Bsz * HALF * Mpts];    // (B, 128, M)

// exact XLA-style distance: ((dx*dx + dy*dy) + dz*dz), rn, no FMA contraction
__device__ __forceinline__ float dist2_exact(float dx, float dy, float dz) {
    return __fadd_rn(__fadd_rn(__fmul_rn(dx, dx), __fmul_rn(dy, dy)),
                     __fmul_rn(dz, dz));
}

// ---------------- f32x2 packed helpers (exact per-element rn) --------------
__device__ __forceinline__ ull pack2(float lo, float hi) {
    ull r; asm("mov.b64 %0, {%1, %2};" : "=l"(r) : "f"(lo), "f"(hi)); return r;
}
__device__ __forceinline__ void unpack2(ull v, uint& lo, uint& hi) {
    asm("mov.b64 {%0, %1}, %2;" : "=r"(lo), "=r"(hi) : "l"(v));
}
__device__ __forceinline__ ull add2(ull a, ull b) {
    ull r; asm("add.rn.f32x2 %0, %1, %2;" : "=l"(r) : "l"(a), "l"(b)); return r;
}
__device__ __forceinline__ ull mul2(ull a, ull b) {
    ull r; asm("mul.rn.f32x2 %0, %1, %2;" : "=l"(r) : "l"(a), "l"(b)); return r;
}
__device__ __forceinline__ uint redux_max_u32(uint v) {
    uint r; asm("redux.sync.max.u32 %0, %1, 0xffffffff;" : "=r"(r) : "r"(v)); return r;
}
__device__ __forceinline__ uint redux_min_u32(uint v) {
    uint r; asm("redux.sync.min.u32 %0, %1, 0xffffffff;" : "=r"(r) : "r"(v)); return r;
}

// ============================================================================
// Kernel A: blocks 0..3 = FPS (one CTA/batch; thin-skip + warp0 combine);
//           blocks 4..  = conv1 GEMM (runs in FPS's shadow).
// ============================================================================
__global__ __launch_bounds__(1024, 1)
void fps_conv1_kernel(const float* __restrict__ p,
                      const float* __restrict__ f,
                      const float* __restrict__ w,      // conv1_w (256,128)
                      const float* __restrict__ bias,   // conv1_b (256)
                      float* __restrict__ newp)         // d_out head (B,M,3)
{
    extern __shared__ char dsm[];
    __shared__ float sA[32 * 64];      // conv1 only
    __shared__ float sW[32 * 257];     // conv1 only
    __shared__ uint   swv[32];         // FPS: per-warp max bits (persistent)
    __shared__ uint   swi[32];         // FPS: per-warp argmax orig index
    __shared__ float4 swc[32];         // FPS: per-warp winner coords
    __shared__ float4 scen;            // FPS: current center (x,y,z,idx)

    if (blockIdx.x < Bsz) {
        // ----------------------------- FPS -------------------------------
        float4* sp4  = (float4*)dsm;                   // [k][t]: k*1024+t
        uint*   hist = (uint*)(dsm + Npts * 16);       // 513

        const int b = blockIdx.x;
        const float* pb = p + (size_t)b * Npts * 3;
        const int t = threadIdx.x, lane = t & 31, wrp = t >> 5;

        // ---- preamble: counting-sort into 512 MORTON-ordered bins ----
        if (t < 512) hist[t] = 0;
        __syncthreads();
        {
            float lx[8], ly[8], lz[8];
            uint  lb[8];
#pragma unroll
            for (int k = 0; k < 8; k++) {
                int i = k * 1024 + t;
                lx[k] = pb[3 * i];
                ly[k] = pb[3 * i + 1];
                lz[k] = pb[3 * i + 2];
                uint bx = (uint)(int)fminf(fmaxf(lx[k], 0.f) * 8.f, 7.f);
                uint by = (uint)(int)fminf(fmaxf(ly[k], 0.f) * 8.f, 7.f);
                uint bz = (uint)(int)fminf(fmaxf(lz[k], 0.f) * 8.f, 7.f);
                lb[k] = ((bx & 4u) << 6) | ((bx & 2u) << 4) | ((bx & 1u) << 2)
                      | ((by & 4u) << 5) | ((by & 2u) << 3) | ((by & 1u) << 1)
                      | ((bz & 4u) << 4) | ((bz & 2u) << 2) |  (bz & 1u);
                atomicAdd(&hist[lb[k]], 1u);
            }
            __syncthreads();
            if (t == 0) {                  // serial exclusive scan (once)
                uint run = 0;
                for (int j = 0; j < 512; j++) {
                    uint c = hist[j]; hist[j] = run; run += c;
                }
            }
            __syncthreads();
#pragma unroll
            for (int k = 0; k < 8; k++) {
                uint pos = atomicAdd(&hist[lb[k]], 1u);
                uint dst = (pos & 7u) * 1024u + (pos >> 3);   // [k][t] layout
                sp4[dst] = make_float4(lx[k], ly[k], lz[k],
                                       __uint_as_float((uint)(k * 1024 + t)));
            }
        }
        __syncthreads();

        // ---- load my 8 sorted points into packed registers + warp bbox ----
        ull PX[4], PY[4], PZ[4];
        uint D[8];
        float wlox, whix, wloy, whiy, wloz, whiz;
        {
            float qx[8], qy[8], qz[8];
#pragma unroll
            for (int k = 0; k < 8; k++) {
                float4 q = sp4[k * 1024 + t];        // conflict-free
                qx[k] = q.x; qy[k] = q.y; qz[k] = q.z;
                D[k] = __float_as_uint(1e10f);
            }
#pragma unroll
            for (int j = 0; j < 4; j++) {
                PX[j] = pack2(qx[2 * j], qx[2 * j + 1]);
                PY[j] = pack2(qy[2 * j], qy[2 * j + 1]);
                PZ[j] = pack2(qz[2 * j], qz[2 * j + 1]);
            }
            float alox = qx[0], ahix = qx[0], aloy = qy[0], ahiy = qy[0];
            float aloz = qz[0], ahiz = qz[0];
#pragma unroll
            for (int k = 1; k < 8; k++) {
                alox = fminf(alox, qx[k]); ahix = fmaxf(ahix, qx[k]);
                aloy = fminf(aloy, qy[k]); ahiy = fmaxf(ahiy, qy[k]);
                aloz = fminf(aloz, qz[k]); ahiz = fmaxf(ahiz, qz[k]);
            }
#pragma unroll
            for (int off = 16; off > 0; off >>= 1) {
                alox = fminf(alox, __shfl_xor_sync(FULLMASK, alox, off));
                ahix = fmaxf(ahix, __shfl_xor_sync(FULLMASK, ahix, off));
                aloy = fminf(aloy, __shfl_xor_sync(FULLMASK, aloy, off));
                ahiy = fmaxf(ahiy, __shfl_xor_sync(FULLMASK, ahiy, off));
                aloz = fminf(aloz, __shfl_xor_sync(FULLMASK, aloz, off));
                ahiz = fmaxf(ahiz, __shfl_xor_sync(FULLMASK, ahiz, off));
            }
            wlox = alox; whix = ahix; wloy = aloy; whiy = ahiy;
            wloz = aloz; whiz = ahiz;
        }

        uint wmaxc = __float_as_uint(1e10f);   // this warp's own cached max

        if (t == 0) {
            float x0 = __ldg(&pb[0]), y0 = __ldg(&pb[1]), z0 = __ldg(&pb[2]);
            scen = make_float4(x0, y0, z0, 0.f);
            g_idx[b * Mpts] = 0;
            newp[(size_t)(b * Mpts) * 3 + 0] = x0;
            newp[(size_t)(b * Mpts) * 3 + 1] = y0;
            newp[(size_t)(b * Mpts) * 3 + 2] = z0;
        }
        __syncthreads();

        for (int m = 1; m < Mpts; m++) {
            // center chosen at m-1 (broadcast LDS)
            const float4 c = scen;
            const float cx = c.x, cy = c.y, cz = c.z;

            // ---- warp-uniform thin skip test ----
            float gx = fmaxf(fmaxf(wlox - cx, cx - whix), 0.f);
            float gy = fmaxf(fmaxf(wloy - cy, cy - whiy), 0.f);
            float gz = fmaxf(fmaxf(wloz - cz, cz - whiz), 0.f);
            float d2m = gx * gx + gy * gy + gz * gz;
            if (!(d2m * 0.99f >= __uint_as_float(wmaxc))) {
                // ---- packed exact-rn update of my 8 distances ----
                ull ncx = pack2(-cx, -cx), ncy = pack2(-cy, -cy), ncz = pack2(-cz, -cz);
#pragma unroll
                for (int pr = 0; pr < 4; pr++) {
                    ull dx = add2(PX[pr], ncx);
                    ull dy = add2(PY[pr], ncy);
                    ull dz = add2(PZ[pr], ncz);
                    ull d2 = add2(add2(mul2(dx, dx), mul2(dy, dy)), mul2(dz, dz));
                    uint lo, hi; unpack2(d2, lo, hi);
                    uint a = D[2 * pr];       D[2 * pr]     = (lo < a) ? lo : a;
                    uint cc2 = D[2 * pr + 1]; D[2 * pr + 1] = (hi < cc2) ? hi : cc2;
                }
                // per-thread argmax scan, original-index tie-break from sp4.w
                uint bd = 0, bg = 0; int bk = 0;
#pragma unroll
                for (int k = 0; k < 8; k++) {
                    uint gi = *(const uint*)((const char*)sp4
                                             + ((size_t)(k * 1024 + t) * 16u + 12u));
                    uint nw = D[k];
                    bool better = (k == 0) || (nw > bd) || (nw == bd && gi < bg);
                    if (better) { bd = nw; bg = gi; bk = k; }
                }
                // warp argmax + refresh persistent per-warp entries
                uint wmax = redux_max_u32(bd);
                uint cand = (bd == wmax) ? bg : 0xffffffffu;
                uint widx = redux_min_u32(cand);
                if (bd == wmax && bg == widx) {           // unique owner lane
                    swc[wrp] = sp4[bk * 1024 + t];
                }
                if (lane == 0) { swv[wrp] = wmax; swi[wrp] = widx; }
                wmaxc = wmax;
            }
            __syncthreads();                              // BAR_a

            if (wrp == 0) {
                uint v  = swv[lane];
                uint ii = swi[lane];
                uint gm = redux_max_u32(v);
                uint c2 = (v == gm) ? ii : 0xffffffffu;
                uint bi = redux_min_u32(c2);
                uint wm = __ballot_sync(FULLMASK, c2 == bi);  // v==gm && ii==bi
                int  wwin = __ffs(wm) - 1;                    // uniform
                float4 cc = swc[wwin];                        // broadcast LDS.128
                if (lane == 0) {
                    scen = make_float4(cc.x, cc.y, cc.z, 0.f);
                    g_idx[b * Mpts + m] = (int)bi;
                    float* o = newp + (size_t)(b * Mpts + m) * 3;
                    o[0] = cc.x; o[1] = cc.y; o[2] = cc.z;
                }
            }
            __syncthreads();                              // BAR_b
        }
    } else {
        // ------------------- conv1: f1t[b][n][c] = W @ f + bias ----------
        const int bc = blockIdx.x - Bsz;
        const int b  = bc >> 7;                 // 128 x-tiles per batch
        const int x0 = (bc & 127) * 64;
        const int t  = threadIdx.x;
        const int tx = t & 31;                  // c = tx + 32k
        const int ty = t >> 5;                  // x = x0 + ty*2 + e
        const float* fb = f + (size_t)b * CIN * Npts;

        float acc[2][8];
#pragma unroll
        for (int e = 0; e < 2; e++)
#pragma unroll
            for (int k = 0; k < 8; k++) acc[e][k] = 0.f;

        for (int cic = 0; cic < CIN; cic += 32) {
#pragma unroll
            for (int e = 0; e < 2; e++) {
                int lin = e * 1024 + t;
                int ci = lin >> 6, xl = lin & 63;
                sA[ci * 64 + xl] = fb[(size_t)(cic + ci) * Npts + x0 + xl];
            }
#pragma unroll
            for (int e = 0; e < 8; e++) {
                int lin = e * 1024 + t;
                int c = lin >> 5, ci = lin & 31;
                sW[ci * 257 + c] = w[c * CIN + cic + ci];
            }
            __syncthreads();
#pragma unroll
            for (int ci = 0; ci < 32; ci++) {
                float a0 = sA[ci * 64 + ty * 2];
                float a1 = sA[ci * 64 + ty * 2 + 1];
#pragma unroll
                for (int k = 0; k < 8; k++) {
                    float wv = sW[ci * 257 + tx + 32 * k];
                    acc[0][k] = fmaf(a0, wv, acc[0][k]);
                    acc[1][k] = fmaf(a1, wv, acc[1][k]);
                }
            }
            __syncthreads();
        }
#pragma unroll
        for (int e = 0; e < 2; e++) {
            int x = x0 + ty * 2 + e;
            float* orow = g_f1t + (size_t)(b * Npts + x) * COUT;
#pragma unroll
            for (int k = 0; k < 8; k++) {
                int c = tx + 32 * k;
                orow[c] = acc[e][k] + bias[c];
            }
        }
    }
}

// ============================================================================
// Kernel B: blocks x<128: ball query + dpn + theta + tmax (warp per center);
//           blocks x>=128: gather fi[b][ci][m] = f[b][ci][idx[b][m]].
// ============================================================================
#define BALLQ_SMEM ((3 * Npts + 3 * NDIR + 16 * KNB) * 4)

__global__ __launch_bounds__(512)
void ballq_gather_kernel(const float* __restrict__ p,
                         const float* __restrict__ newp,
                         const float* __restrict__ dirs,
                         const float* __restrict__ f)
{
    extern __shared__ float sh[];
    const int b = blockIdx.y;
    const int t = threadIdx.x;

    if (blockIdx.x >= Mpts / 16) {
        // ---------------- gather fi ----------------
        const int ci = blockIdx.x - Mpts / 16;
        const float* fb = f + (size_t)(b * CIN + ci) * Npts;
        float* ob = g_fi + (size_t)(b * CIN + ci) * Mpts;
        const int* ib = g_idx + b * Mpts;
        for (int m = t; m < Mpts; m += 512)
            ob[m] = fb[ib[m]];
        return;
    }

    float* spx = sh;
    float* spy = sh + Npts;
    float* spz = sh + 2 * Npts;
    float* sdx = sh + 3 * Npts;
    float* sdy = sdx + NDIR;
    float* sdz = sdy + NDIR;
    int*   sq  = (int*)(sdz + NDIR);

    const int w = t >> 5, lane = t & 31;
    const float* pb = p + (size_t)b * Npts * 3;

    for (int n = t; n < Npts; n += 512) {
        spx[n] = pb[3 * n];
        spy[n] = pb[3 * n + 1];
        spz[n] = pb[3 * n + 2];
    }
    if (t < NDIR) {
        float dx = dirs[3 * t], dy = dirs[3 * t + 1], dz = dirs[3 * t + 2];
        float nm = sqrtf(dx * dx + dy * dy + dz * dz);
        float inv = 1.0f / fmaxf(nm, 1e-12f);
        sdx[t] = dx * inv; sdy[t] = dy * inv; sdz[t] = dz * inv;
    }
    __syncthreads();

    const int m = blockIdx.x * 16 + w;
    const float* cp = newp + (size_t)(b * Mpts + m) * 3;
    const float cx = cp[0], cy = cp[1], cz = cp[2];

    int cnt = 0;
    int* q = sq + w * KNB;
    for (int ch = 0; ch < Npts / 32; ch++) {
        int n = ch * 32 + lane;
        float dx = spx[n] - cx, dy = spy[n] - cy, dz = spz[n] - cz;
        float d2 = dist2_exact(dx, dy, dz);
        bool pred = d2 < BQ_R2;
        unsigned mask = __ballot_sync(FULLMASK, pred);
        if (pred) {
            int pos = cnt + __popc(mask & ((1u << lane) - 1u));
            if (pos < KNB) q[pos] = n;
        }
        cnt += __popc(mask);
        if (cnt >= KNB) break;
    }
    __syncwarp();
    int eff = cnt < KNB ? cnt : KNB;
    int myn = q[lane < eff ? lane : 0];
    g_qidx[(b * Mpts + m) * KNB + lane] = myn;

    float dx = spx[myn] - cx, dy = spy[myn] - cy, dz = spz[myn] - cz;
    float nm = sqrtf(dx * dx + dy * dy + dz * dz);
    float inv = 1.0f / fmaxf(nm, 1e-12f);
    float ux = dx * inv, uy = dy * inv, uz = dz * inv;

    float mytm = 0.f;
#pragma unroll
    for (int d = 0; d < NDIR; d++) {
        float th = ux * sdx[d] + uy * sdy[d] + uz * sdz[d];
#pragma unroll
        for (int off = 16; off > 0; off >>= 1)
            th = fmaxf(th, __shfl_xor_sync(FULLMASK, th, off));
        if (lane == d) mytm = th;
    }
    g_tmax[((size_t)b * NDIR + lane) * Mpts + m] = mytm;
}

// ============================================================================
// Shared GEMM body: out[b][c][x] = sum_ci W[c][ci]*A[b][ci][x] (+epilogue)
// mode 0: identity  (A=g_fi,   out=outf, write acc+bias)
// mode 1: h         (A=g_tmax, out=g_h,  bn + exact gelu)
// mode 2: pe        (A=g_h,    out=outf, out += acc+bias)
// ============================================================================
__device__ __forceinline__
void gemm_body(const float* __restrict__ W, const float* __restrict__ bias,
               const float* __restrict__ bg, const float* __restrict__ bb,
               const float* __restrict__ bm, const float* __restrict__ bvv,
               float* __restrict__ outf, int Cin, int Cout, int mode, int co0,
               float* sA, float* sW)
{
    const int b = blockIdx.z;
    const int m0 = blockIdx.x * 64;
    const int t = threadIdx.x, tx = t & 15, ty = t >> 4;

    const float* A = (mode == 0) ? g_fi : (mode == 1 ? g_tmax : g_h);
    float* out = (mode == 1) ? g_h : outf;
    const float* Ab = A + (size_t)b * Cin * Mpts;

    float acc[4][4];
#pragma unroll
    for (int j = 0; j < 4; j++)
#pragma unroll
        for (int i = 0; i < 4; i++) acc[j][i] = 0.f;

    for (int cic = 0; cic < Cin; cic += 32) {
#pragma unroll
        for (int e = 0; e < 8; e++) {
            int lin = e * 256 + t;
            int ci = lin >> 6, xl = lin & 63;
            sA[ci * 64 + xl] = Ab[(size_t)(cic + ci) * Mpts + m0 + xl];
            int co = lin >> 5, ci2 = lin & 31;
            sW[co * 33 + ci2] = W[(size_t)(co0 + co) * Cin + cic + ci2];
        }
        __syncthreads();
#pragma unroll
        for (int ci = 0; ci < 32; ci++) {
            float4 a = *(const float4*)&sA[ci * 64 + tx * 4];
#pragma unroll
            for (int j = 0; j < 4; j++) {
                float wv = sW[(ty * 4 + j) * 33 + ci];
                acc[j][0] = fmaf(wv, a.x, acc[j][0]);
                acc[j][1] = fmaf(wv, a.y, acc[j][1]);
                acc[j][2] = fmaf(wv, a.z, acc[j][2]);
                acc[j][3] = fmaf(wv, a.w, acc[j][3]);
            }
        }
        __syncthreads();
    }

#pragma unroll
    for (int j = 0; j < 4; j++) {
        int c = co0 + ty * 4 + j;
        size_t o = ((size_t)b * Cout + c) * Mpts + m0 + tx * 4;
        float r[4] = {acc[j][0], acc[j][1], acc[j][2], acc[j][3]};
        if (mode == 0) {
            float bc = bias[c];
            float4 v = make_float4(r[0] + bc, r[1] + bc, r[2] + bc, r[3] + bc);
            *(float4*)&out[o] = v;
        } else if (mode == 1) {
            float scale = bg[c] / sqrtf(bvv[c] + BNEPS);
            float mean = bm[c], off = bb[c];
            float4 v;
            float* pv = &v.x;
#pragma unroll
            for (int i = 0; i < 4; i++) {
                float y = (r[i] - mean) * scale + off;
                pv[i] = 0.5f * y * (1.0f + erff(y * 0.70710678118654752f));
            }
            *(float4*)&out[o] = v;
        } else {
            float bc = bias[c];
            float4 old = *(const float4*)&out[o];
            float4 v = make_float4(old.x + r[0] + bc, old.y + r[1] + bc,
                                   old.z + r[2] + bc, old.w + r[3] + bc);
            *(float4*)&out[o] = v;
        }
    }
}

// Combined identity (mode 0, y in [0,4)) + h (mode 1, y in [4,6)) launch.
__global__ __launch_bounds__(256)
void gemm01_kernel(const float* __restrict__ skip_w, const float* __restrict__ skip_b,
                   const float* __restrict__ de_w1,
                   const float* __restrict__ de_g, const float* __restrict__ de_bb,
                   const float* __restrict__ de_m, const float* __restrict__ de_v,
                   float* __restrict__ outf)
{
    __shared__ float sA[32 * 64];
    __shared__ float sW[64 * 33];
    if (blockIdx.y < COUT / 64) {
        gemm_body(skip_w, skip_b, nullptr, nullptr, nullptr, nullptr,
                  outf, CIN, COUT, 0, blockIdx.y * 64, sA, sW);
    } else {
        gemm_body(de_w1, nullptr, de_g, de_bb, de_m, de_v,
                  outf, NDIR, HALF, 1, (blockIdx.y - COUT / 64) * 64, sA, sW);
    }
}

// pe GEMM (mode 2)
__global__ __launch_bounds__(256)
void gemm2_kernel(const float* __restrict__ de_w2, const float* __restrict__ de_b2,
                  float* __restrict__ outf)
{
    __shared__ float sA[32 * 64];
    __shared__ float sW[64 * 33];
    gemm_body(de_w2, de_b2, nullptr, nullptr, nullptr, nullptr,
              outf, HALF, COUT, 2, blockIdx.y * 64, sA, sW);
}

// ============================================================================
// Kernel E: fj gather-max over K + bn1, += into outf. Warp per center m.
// ============================================================================
__global__ __launch_bounds__(1024)
void fjmax_kernel(const float* __restrict__ bg, const float* __restrict__ bb,
                  const float* __restrict__ bm, const float* __restrict__ bvv,
                  float* __restrict__ outf)
{
    __shared__ float st[COUT * 33];
    const int b = blockIdx.y, m0 = blockIdx.x * 32;
    const int t = threadIdx.x, w = t >> 5, lane = t & 31;
    const int m = m0 + w;

    int kn = g_qidx[(b * Mpts + m) * KNB + lane];
    int first = __shfl_sync(FULLMASK, kn, 0);

    float4 a0 = make_float4(-3.4e38f, -3.4e38f, -3.4e38f, -3.4e38f);
    float4 a1 = a0;
    for (int k = 0; k < KNB; k++) {
        int n = __shfl_sync(FULLMASK, kn, k);
        if (k > 0 && n == first) continue;   // uniform across warp
        const float4* row = (const float4*)(g_f1t + (size_t)(b * Npts + n) * COUT);
        float4 v0 = row[lane];
        float4 v1 = row[32 + lane];
        a0.x = fmaxf(a0.x, v0.x); a0.y = fmaxf(a0.y, v0.y);
        a0.z = fmaxf(a0.z, v0.z); a0.w = fmaxf(a0.w, v0.w);
        a1.x = fmaxf(a1.x, v1.x); a1.y = fmaxf(a1.y, v1.y);
        a1.z = fmaxf(a1.z, v1.z); a1.w = fmaxf(a1.w, v1.w);
    }
    const float* pa0 = &a0.x;
    const float* pa1 = &a1.x;
#pragma unroll
    for (int j = 0; j < 4; j++) {
        st[(lane * 4 + j) * 33 + w] = pa0[j];
        st[(128 + lane * 4 + j) * 33 + w] = pa1[j];
    }
    __syncthreads();

    const int c = t >> 2, part = t & 3;
    float scale = bg[c] / sqrtf(bvv[c] + BNEPS);
    float mean = bm[c], off = bb[c];
    float* o = outf + ((size_t)b * COUT + c) * Mpts + m0 + part * 8;
#pragma unroll
    for (int i = 0; i < 8; i++) {
        float x = st[c * 33 + part * 8 + i];
        o[i] += (x - mean) * scale + off;
    }
}

// ============================================================================
extern "C" void kernel_launch(void* const* d_in, const int* in_sizes, int n_in,
                              void* d_out, int out_size)
{
    const float* p       = (const float*)d_in[0];
    const float* f       = (const float*)d_in[1];
    const float* conv1_w = (const float*)d_in[2];
    const float* conv1_b = (const float*)d_in[3];
    const float* skip_w  = (const float*)d_in[4];
    const float* skip_b  = (const float*)d_in[5];
    const float* bn1_g   = (const float*)d_in[6];
    const float* bn1_b   = (const float*)d_in[7];
    const float* bn1_m   = (const float*)d_in[8];
    const float* bn1_v   = (const float*)d_in[9];
    const float* dirs    = (const float*)d_in[10];
    const float* de_w1   = (const float*)d_in[11];
    const float* de_g    = (const float*)d_in[12];
    const float* de_bb   = (const float*)d_in[13];
    const float* de_m    = (const float*)d_in[14];
    const float* de_v    = (const float*)d_in[15];
    const float* de_w2   = (const float*)d_in[16];
    const float* de_b2   = (const float*)d_in[17];

    float* outp = (float*)d_out;                 // new_p (B,M,3)
    float* outf = outp + Bsz * Mpts * 3;         // f_out (B,256,M)

    cudaFuncSetAttribute(fps_conv1_kernel,
                         cudaFuncAttributeMaxDynamicSharedMemorySize, FPS_DYN);
    cudaFuncSetAttribute(ballq_gather_kernel,
                         cudaFuncAttributeMaxDynamicSharedMemorySize, BALLQ_SMEM);

    // 1) FPS (4 blocks, thin-skip + warp0 combine) + conv1 GEMM (512 blocks)
    fps_conv1_kernel<<<Bsz + Bsz * 128, 1024, FPS_DYN>>>(p, f, conv1_w, conv1_b, outp);
    // 2) ball query + theta + tmax  ||  gather fi   (one launch)
    ballq_gather_kernel<<<dim3(Mpts / 16 + CIN, Bsz), 512, BALLQ_SMEM>>>(
        p, outp, dirs, f);
    // 3) identity -> outf (write)  ||  h = gelu(bn(de_w1 @ tmax)) -> g_h
    gemm01_kernel<<<dim3(Mpts / 64, COUT / 64 + HALF / 64, Bsz), 256>>>(
        skip_w, skip_b, de_w1, de_g, de_bb, de_m, de_v, outf);
    // 4) pe: outf += de_w2 @ h + de_b2
    gemm2_kernel<<<dim3(Mpts / 64, COUT / 64, Bsz), 256>>>(de_w2, de_b2, outf);
    // 5) outf += bn1(max_k fj)
    fjmax_kernel<<<dim3(Mpts / 32, Bsz), 1024>>>(bn1_g, bn1_b, bn1_m, bn1_v, outf);
}